// round 1
// baseline (speedup 1.0000x reference)
#include <cuda_runtime.h>
#include <cuda_bf16.h>
#include <math_constants.h>

// Problem dims
#define BB   2
#define SS   2048
#define HID  2048
#define NH   16
#define NKV  4
#define HD   128
#define RR   64
#define NTOK (BB*SS)          // 4096
#define QKVO ((NH+2*NKV)*HD)  // 3072

// Scratch (device globals; no allocation allowed)
__device__ float g_qkv[(size_t)NTOK * QKVO];          // 50.3 MB
__device__ float g_q[(size_t)BB * NH  * SS * HD];     // 33.5 MB
__device__ float g_k[(size_t)BB * NKV * SS * HD];     //  8.4 MB
__device__ float g_v[(size_t)BB * NKV * SS * HD];     //  8.4 MB
__device__ float g_attn[(size_t)NTOK * (NH*HD)];      // 33.5 MB

// ---------------------------------------------------------------------------
// Generic GEMM: C[M,N] = A[M,K] * B[N,K]^T   (both row-major)
// 128x128 tile, BK=16, 256 threads, 8x8 micro-tile.
// ---------------------------------------------------------------------------
__global__ __launch_bounds__(256) void gemm_tn_kernel(
    const float* __restrict__ A, const float* __restrict__ Bm,
    float* __restrict__ C, int M, int N, int K)
{
    __shared__ float As[16][132];
    __shared__ float Bs[16][132];

    const int tid = threadIdx.x;
    const int ty = tid >> 4;        // 0..15
    const int tx = tid & 15;        // 0..15
    const int row0 = blockIdx.y * 128;
    const int col0 = blockIdx.x * 128;

    const int lrow = tid >> 2;          // 0..63
    const int lcol = (tid & 3) * 4;     // 0,4,8,12

    float acc[8][8];
    #pragma unroll
    for (int i = 0; i < 8; ++i)
        #pragma unroll
        for (int j = 0; j < 8; ++j) acc[i][j] = 0.f;

    for (int k0 = 0; k0 < K; k0 += 16) {
        #pragma unroll
        for (int p = 0; p < 2; ++p) {
            int r = lrow + p * 64;
            float4 va = *(const float4*)&A[(size_t)(row0 + r) * K + k0 + lcol];
            As[lcol + 0][r] = va.x; As[lcol + 1][r] = va.y;
            As[lcol + 2][r] = va.z; As[lcol + 3][r] = va.w;
            float4 vb = *(const float4*)&Bm[(size_t)(col0 + r) * K + k0 + lcol];
            Bs[lcol + 0][r] = vb.x; Bs[lcol + 1][r] = vb.y;
            Bs[lcol + 2][r] = vb.z; Bs[lcol + 3][r] = vb.w;
        }
        __syncthreads();

        #pragma unroll
        for (int k = 0; k < 16; ++k) {
            float ra[8], rb[8];
            *(float4*)&ra[0] = *(const float4*)&As[k][ty * 8];
            *(float4*)&ra[4] = *(const float4*)&As[k][ty * 8 + 4];
            *(float4*)&rb[0] = *(const float4*)&Bs[k][tx * 8];
            *(float4*)&rb[4] = *(const float4*)&Bs[k][tx * 8 + 4];
            #pragma unroll
            for (int i = 0; i < 8; ++i)
                #pragma unroll
                for (int j = 0; j < 8; ++j)
                    acc[i][j] = fmaf(ra[i], rb[j], acc[i][j]);
        }
        __syncthreads();
    }

    #pragma unroll
    for (int i = 0; i < 8; ++i) {
        size_t off = (size_t)(row0 + ty * 8 + i) * N + col0 + tx * 8;
        float4 v0 = make_float4(acc[i][0], acc[i][1], acc[i][2], acc[i][3]);
        float4 v1 = make_float4(acc[i][4], acc[i][5], acc[i][6], acc[i][7]);
        *(float4*)&C[off] = v0;
        *(float4*)&C[off + 4] = v1;
    }
}

// ---------------------------------------------------------------------------
// Per-head RMSNorm + RoPE + split into Q/K/V tensors.
// grid = (24 heads, S, B), 128 threads (one per dim).
// ---------------------------------------------------------------------------
__global__ __launch_bounds__(128) void prep_kernel(
    const float* __restrict__ cos_t, const float* __restrict__ sin_t,
    const float* __restrict__ q_ln, const float* __restrict__ k_ln)
{
    const int hh = blockIdx.x;   // 0..23: 0-15 Q heads, 16-19 K, 20-23 V
    const int s  = blockIdx.y;
    const int b  = blockIdx.z;
    const int d  = threadIdx.x;

    const size_t t = (size_t)b * SS + s;
    float x = g_qkv[t * QKVO + hh * HD + d];

    __shared__ float sy[HD];
    __shared__ float red[4];

    if (hh < NH + NKV) {
        // RMSNorm over D
        float sq = x * x;
        #pragma unroll
        for (int o = 16; o; o >>= 1) sq += __shfl_xor_sync(0xFFFFFFFFu, sq, o);
        if ((d & 31) == 0) red[d >> 5] = sq;
        __syncthreads();
        float var = (red[0] + red[1] + red[2] + red[3]) * (1.f / HD);
        const float* w = (hh < NH) ? q_ln : k_ln;
        float y = x * rsqrtf(var + 1e-6f) * w[d];
        sy[d] = y;
        __syncthreads();

        float out = y;
        if (d < RR) {
            float c  = cos_t[t * RR + d];
            float sn = sin_t[t * RR + d];
            float rot = (d < RR / 2) ? -sy[d + RR / 2] : sy[d - RR / 2];
            out = fmaf(y, c, rot * sn);
        }
        if (hh < NH)
            g_q[(((size_t)(b * NH + hh)) * SS + s) * HD + d] = out;
        else
            g_k[(((size_t)(b * NKV + (hh - NH))) * SS + s) * HD + d] = out;
    } else {
        g_v[(((size_t)(b * NKV + (hh - NH - NKV))) * SS + s) * HD + d] = x;
    }
}

// ---------------------------------------------------------------------------
// Flash attention: block = (64 queries) x (b,h). 256 threads.
// Score tile 64x64 (4x4 per thread), O tile 64x128 (4x8 per thread).
// Dynamic smem.
// ---------------------------------------------------------------------------
#define QT_STRIDE 65
#define SMEM_FLOATS (128*65 + 128*65 + 64*128 + 64*65 + 64*16 + 4*64)
#define ATTN_SMEM_BYTES (SMEM_FLOATS * 4)

__global__ __launch_bounds__(256) void attn_kernel()
{
    extern __shared__ float sm[];
    float* Qt    = sm;                 // [128][65] transposed, pre-scaled
    float* Kt    = Qt + 128 * 65;      // [128][65] transposed
    float* Vs    = Kt + 128 * 65;      // [64][128] row-major
    float* Ps    = Vs + 64 * 128;      // [64][65]
    float* sRed  = Ps + 64 * 65;       // [64][16]
    float* sM    = sRed + 64 * 16;     // [64]
    float* sL    = sM + 64;
    float* sScale= sL + 64;
    float* sMnew = sScale + 64;

    const int tid = threadIdx.x;
    const int ty = tid >> 4;      // 0..15 -> query rows ty*4..+3
    const int tx = tid & 15;      // 0..15 -> score cols tx*4..+3 / O cols tx*8..+7
    const int q0 = blockIdx.x * 64;
    const int bh = blockIdx.y;    // 0..31
    const int b = bh >> 4;
    const int h = bh & 15;
    const int hk = h / (NH / NKV);

    const float qscale = 0.08838834764831845f;  // 1/sqrt(128)

    // Load Q (transposed, pre-scaled); init stats
    {
        const float* qsrc = &g_q[(((size_t)(b * NH + h)) * SS + q0) * HD];
        for (int idx = tid; idx < 64 * 128; idx += 256) {
            int r = idx >> 7, d = idx & 127;
            Qt[d * QT_STRIDE + r] = qsrc[idx] * qscale;
        }
        if (tid < 64) { sM[tid] = -CUDART_INF_F; sL[tid] = 0.f; }
    }
    __syncthreads();

    float O[4][8];
    #pragma unroll
    for (int i = 0; i < 4; ++i)
        #pragma unroll
        for (int j = 0; j < 8; ++j) O[i][j] = 0.f;

    const float* kbase = &g_k[((size_t)(b * NKV + hk)) * SS * HD];
    const float* vbase = &g_v[((size_t)(b * NKV + hk)) * SS * HD];

    for (int k0 = 0; k0 < SS; k0 += 64) {
        // Load K (transposed) and V (row-major) tiles
        const float* ks = kbase + (size_t)k0 * HD;
        const float* vs = vbase + (size_t)k0 * HD;
        for (int idx = tid; idx < 64 * 128; idx += 256) {
            int r = idx >> 7, d = idx & 127;
            Kt[d * QT_STRIDE + r] = ks[idx];
            Vs[idx] = vs[idx];
        }
        __syncthreads();

        // Scores: 4x4 per thread
        float sc[4][4];
        #pragma unroll
        for (int i = 0; i < 4; ++i)
            #pragma unroll
            for (int j = 0; j < 4; ++j) sc[i][j] = 0.f;

        #pragma unroll 4
        for (int d = 0; d < 128; ++d) {
            float qa[4], kb[4];
            #pragma unroll
            for (int i = 0; i < 4; ++i) qa[i] = Qt[d * QT_STRIDE + ty * 4 + i];
            #pragma unroll
            for (int j = 0; j < 4; ++j) kb[j] = Kt[d * QT_STRIDE + tx * 4 + j];
            #pragma unroll
            for (int i = 0; i < 4; ++i)
                #pragma unroll
                for (int j = 0; j < 4; ++j)
                    sc[i][j] = fmaf(qa[i], kb[j], sc[i][j]);
        }

        // Row maxes
        #pragma unroll
        for (int i = 0; i < 4; ++i) {
            float m = fmaxf(fmaxf(sc[i][0], sc[i][1]), fmaxf(sc[i][2], sc[i][3]));
            sRed[(ty * 4 + i) * 16 + tx] = m;
        }
        __syncthreads();

        if (tid < 64) {
            float m = sM[tid];
            float tm = -CUDART_INF_F;
            #pragma unroll
            for (int t = 0; t < 16; ++t) tm = fmaxf(tm, sRed[tid * 16 + t]);
            float mn = fmaxf(m, tm);
            sScale[tid] = __expf(m - mn);
            sMnew[tid]  = mn;
            sM[tid]     = mn;
        }
        __syncthreads();

        // Exp, write P, partial row sums, rescale O
        float rsum[4] = {0.f, 0.f, 0.f, 0.f};
        #pragma unroll
        for (int i = 0; i < 4; ++i) {
            float mn = sMnew[ty * 4 + i];
            #pragma unroll
            for (int j = 0; j < 4; ++j) {
                float p = __expf(sc[i][j] - mn);
                Ps[(ty * 4 + i) * QT_STRIDE + tx * 4 + j] = p;
                rsum[i] += p;
            }
        }
        #pragma unroll
        for (int i = 0; i < 4; ++i) sRed[(ty * 4 + i) * 16 + tx] = rsum[i];
        #pragma unroll
        for (int i = 0; i < 4; ++i) {
            float osc = sScale[ty * 4 + i];
            #pragma unroll
            for (int j = 0; j < 8; ++j) O[i][j] *= osc;
        }
        __syncthreads();

        if (tid < 64) {
            float s = 0.f;
            #pragma unroll
            for (int t = 0; t < 16; ++t) s += sRed[tid * 16 + t];
            sL[tid] = sL[tid] * sScale[tid] + s;
        }

        // PV: O[q][c] += sum_kk P[q][kk] * V[kk][c]
        #pragma unroll 4
        for (int kk = 0; kk < 64; ++kk) {
            float pv[4], vv[8];
            #pragma unroll
            for (int i = 0; i < 4; ++i) pv[i] = Ps[(ty * 4 + i) * QT_STRIDE + kk];
            *(float4*)&vv[0] = *(const float4*)&Vs[kk * 128 + tx * 8];
            *(float4*)&vv[4] = *(const float4*)&Vs[kk * 128 + tx * 8 + 4];
            #pragma unroll
            for (int i = 0; i < 4; ++i)
                #pragma unroll
                for (int j = 0; j < 8; ++j)
                    O[i][j] = fmaf(pv[i], vv[j], O[i][j]);
        }
        __syncthreads();
    }

    // Normalize and write out: g_attn[b, s, h*128 + c]
    #pragma unroll
    for (int i = 0; i < 4; ++i) {
        int s = q0 + ty * 4 + i;
        float inv = 1.f / sL[ty * 4 + i];
        size_t off = (((size_t)b * SS + s) * NH + h) * HD + tx * 8;
        float4 v0 = make_float4(O[i][0] * inv, O[i][1] * inv, O[i][2] * inv, O[i][3] * inv);
        float4 v1 = make_float4(O[i][4] * inv, O[i][5] * inv, O[i][6] * inv, O[i][7] * inv);
        *(float4*)&g_attn[off] = v0;
        *(float4*)&g_attn[off + 4] = v1;
    }
}

// ---------------------------------------------------------------------------
extern "C" void kernel_launch(void* const* d_in, const int* in_sizes, int n_in,
                              void* d_out, int out_size)
{
    const float* hidden  = (const float*)d_in[0];
    const float* cos_t   = (const float*)d_in[1];
    const float* sin_t   = (const float*)d_in[2];
    const float* w_qkv   = (const float*)d_in[3];
    const float* q_ln    = (const float*)d_in[4];
    const float* k_ln    = (const float*)d_in[5];
    const float* w_dense = (const float*)d_in[6];
    float* out = (float*)d_out;

    void *p_qkv = nullptr, *p_attn = nullptr;
    cudaGetSymbolAddress(&p_qkv, g_qkv);
    cudaGetSymbolAddress(&p_attn, g_attn);
    float* qkv  = (float*)p_qkv;
    float* attn = (float*)p_attn;

    // 1) QKV projection: [4096,3072] = hidden[4096,2048] * w_qkv[3072,2048]^T
    gemm_tn_kernel<<<dim3(QKVO / 128, NTOK / 128), 256>>>(
        hidden, w_qkv, qkv, NTOK, QKVO, HID);

    // 2) RMSNorm + RoPE + split
    prep_kernel<<<dim3(NH + 2 * NKV, SS, BB), 128>>>(cos_t, sin_t, q_ln, k_ln);

    // 3) Flash attention
    cudaFuncSetAttribute(attn_kernel, cudaFuncAttributeMaxDynamicSharedMemorySize,
                         ATTN_SMEM_BYTES);
    attn_kernel<<<dim3(SS / 64, BB * NH), 256, ATTN_SMEM_BYTES>>>();

    // 4) Output projection: [4096,2048] = attn[4096,2048] * w_dense[2048,2048]^T
    gemm_tn_kernel<<<dim3(HID / 128, NTOK / 128), 256>>>(
        attn, w_dense, out, NTOK, HID, HID * 1);
}

// round 3
// speedup vs baseline: 1.1614x; 1.1614x over previous
#include <cuda_runtime.h>
#include <cuda_bf16.h>
#include <math_constants.h>
#include <cstdint>

// Problem dims
#define BB   2
#define SS   2048
#define HID  2048
#define NH   16
#define NKV  4
#define HD   128
#define RR   64
#define NTOK (BB*SS)          // 4096
#define QKVO ((NH+2*NKV)*HD)  // 3072

// Scratch (device globals; no allocation allowed)
__device__ float g_qkv[(size_t)NTOK * QKVO];          // 50.3 MB
__device__ float g_q[(size_t)BB * NH  * SS * HD];     // 33.5 MB
__device__ float g_k[(size_t)BB * NKV * SS * HD];     //  8.4 MB
__device__ float g_v[(size_t)BB * NKV * SS * HD];     //  8.4 MB
__device__ float g_attn[(size_t)NTOK * (NH*HD)];      // 33.5 MB

// ---------------------------------------------------------------------------
// Generic GEMM: C[M,N] = A[M,K] * B[N,K]^T   (both row-major)
// 128x128 tile, BK=16, 256 threads, 8x8 micro-tile.  (proven: 62 TF/s fp32)
// ---------------------------------------------------------------------------
__global__ __launch_bounds__(256) void gemm_tn_kernel(
    const float* __restrict__ A, const float* __restrict__ Bm,
    float* __restrict__ C, int M, int N, int K)
{
    __shared__ float As[16][132];
    __shared__ float Bs[16][132];

    const int tid = threadIdx.x;
    const int ty = tid >> 4;
    const int tx = tid & 15;
    const int row0 = blockIdx.y * 128;
    const int col0 = blockIdx.x * 128;

    const int lrow = tid >> 2;
    const int lcol = (tid & 3) * 4;

    float acc[8][8];
    #pragma unroll
    for (int i = 0; i < 8; ++i)
        #pragma unroll
        for (int j = 0; j < 8; ++j) acc[i][j] = 0.f;

    for (int k0 = 0; k0 < K; k0 += 16) {
        #pragma unroll
        for (int p = 0; p < 2; ++p) {
            int r = lrow + p * 64;
            float4 va = *(const float4*)&A[(size_t)(row0 + r) * K + k0 + lcol];
            As[lcol + 0][r] = va.x; As[lcol + 1][r] = va.y;
            As[lcol + 2][r] = va.z; As[lcol + 3][r] = va.w;
            float4 vb = *(const float4*)&Bm[(size_t)(col0 + r) * K + k0 + lcol];
            Bs[lcol + 0][r] = vb.x; Bs[lcol + 1][r] = vb.y;
            Bs[lcol + 2][r] = vb.z; Bs[lcol + 3][r] = vb.w;
        }
        __syncthreads();

        #pragma unroll
        for (int k = 0; k < 16; ++k) {
            float ra[8], rb[8];
            *(float4*)&ra[0] = *(const float4*)&As[k][ty * 8];
            *(float4*)&ra[4] = *(const float4*)&As[k][ty * 8 + 4];
            *(float4*)&rb[0] = *(const float4*)&Bs[k][tx * 8];
            *(float4*)&rb[4] = *(const float4*)&Bs[k][tx * 8 + 4];
            #pragma unroll
            for (int i = 0; i < 8; ++i)
                #pragma unroll
                for (int j = 0; j < 8; ++j)
                    acc[i][j] = fmaf(ra[i], rb[j], acc[i][j]);
        }
        __syncthreads();
    }

    #pragma unroll
    for (int i = 0; i < 8; ++i) {
        size_t off = (size_t)(row0 + ty * 8 + i) * N + col0 + tx * 8;
        float4 v0 = make_float4(acc[i][0], acc[i][1], acc[i][2], acc[i][3]);
        float4 v1 = make_float4(acc[i][4], acc[i][5], acc[i][6], acc[i][7]);
        *(float4*)&C[off] = v0;
        *(float4*)&C[off + 4] = v1;
    }
}

// ---------------------------------------------------------------------------
// Per-head RMSNorm + RoPE + split into Q/K/V tensors.
// ---------------------------------------------------------------------------
__global__ __launch_bounds__(128) void prep_kernel(
    const float* __restrict__ cos_t, const float* __restrict__ sin_t,
    const float* __restrict__ q_ln, const float* __restrict__ k_ln)
{
    const int hh = blockIdx.x;
    const int s  = blockIdx.y;
    const int b  = blockIdx.z;
    const int d  = threadIdx.x;

    const size_t t = (size_t)b * SS + s;
    float x = g_qkv[t * QKVO + hh * HD + d];

    __shared__ float sy[HD];
    __shared__ float red[4];

    if (hh < NH + NKV) {
        float sq = x * x;
        #pragma unroll
        for (int o = 16; o; o >>= 1) sq += __shfl_xor_sync(0xFFFFFFFFu, sq, o);
        if ((d & 31) == 0) red[d >> 5] = sq;
        __syncthreads();
        float var = (red[0] + red[1] + red[2] + red[3]) * (1.f / HD);
        const float* w = (hh < NH) ? q_ln : k_ln;
        float y = x * rsqrtf(var + 1e-6f) * w[d];
        sy[d] = y;
        __syncthreads();

        float out = y;
        if (d < RR) {
            float c  = cos_t[t * RR + d];
            float sn = sin_t[t * RR + d];
            float rot = (d < RR / 2) ? -sy[d + RR / 2] : sy[d - RR / 2];
            out = fmaf(y, c, rot * sn);
        }
        if (hh < NH)
            g_q[(((size_t)(b * NH + hh)) * SS + s) * HD + d] = out;
        else
            g_k[(((size_t)(b * NKV + (hh - NH))) * SS + s) * HD + d] = out;
    } else {
        g_v[(((size_t)(b * NKV + (hh - NH - NKV))) * SS + s) * HD + d] = x;
    }
}

// ---------------------------------------------------------------------------
// Flash attention v2: Q-tile 128, K-tile 64, 256 threads.
// Score micro-tile 8x4 (ty: 16 groups x 8 q = 128; tx: 16 groups x 4 k = 64).
// PV micro-tile 8x8 (c = tx*8). 1 CTA/SM, ~186 KB smem.
// ---------------------------------------------------------------------------
#define QTS 136     // Qt stride (floats), mult of 8 -> 16B-aligned rows
#define KTS 72      // Kt stride
#define PSS 72      // Ps stride
#define SRS 129     // sRed stride (transposed [16][129])

#define ATTN_SMEM_FLOATS (128*QTS + 128*KTS + 64*128 + 128*PSS + 16*SRS + 4*128)
#define ATTN_SMEM_BYTES  (ATTN_SMEM_FLOATS * 4)

__global__ __launch_bounds__(256, 1) void attn_kernel()
{
    extern __shared__ float smf[];
    float* Qt    = smf;                   // [128 d][QTS]  (transposed, prescaled)
    float* Kt    = Qt + 128 * QTS;        // [128 d][KTS]  (transposed)
    float* Vs    = Kt + 128 * KTS;        // [64 k][128 c]
    float* Ps    = Vs + 64 * 128;         // [128 q][PSS]
    float* sRed  = Ps + 128 * PSS;        // [16 tx][SRS]  (transposed)
    float* sM    = sRed + 16 * SRS;       // [128]
    float* sL    = sM + 128;
    float* sScale= sL + 128;
    float* sMnew = sScale + 128;

    const int tid = threadIdx.x;
    const int ty = tid >> 4;      // 0..15 -> q rows ty*8..+7
    const int tx = tid & 15;      // 0..15 -> k cols tx*4..+3 / c cols tx*8..+7
    const int q0 = blockIdx.x * 128;
    const int bh = blockIdx.y;    // 0..31
    const int b = bh >> 4;
    const int h = bh & 15;
    const int hk = h / (NH / NKV);

    const float qscale = 0.08838834764831845f;  // 1/sqrt(128)

    // Load Q (transposed, pre-scaled); init stats
    {
        const float* qsrc = &g_q[(((size_t)(b * NH + h)) * SS + q0) * HD];
        #pragma unroll
        for (int it = 0; it < 16; ++it) {
            int f4 = tid + it * 256;        // 0..4095 float4s (128 q x 32)
            int r  = f4 >> 5;               // q row 0..127
            int c4 = f4 & 31;               // d group
            float4 v = *(const float4*)&qsrc[(size_t)r * HD + c4 * 4];
            Qt[(c4 * 4 + 0) * QTS + r] = v.x * qscale;
            Qt[(c4 * 4 + 1) * QTS + r] = v.y * qscale;
            Qt[(c4 * 4 + 2) * QTS + r] = v.z * qscale;
            Qt[(c4 * 4 + 3) * QTS + r] = v.w * qscale;
        }
        if (tid < 128) { sM[tid] = -CUDART_INF_F; sL[tid] = 0.f; }
    }
    __syncthreads();

    float O[8][8];
    #pragma unroll
    for (int i = 0; i < 8; ++i)
        #pragma unroll
        for (int j = 0; j < 8; ++j) O[i][j] = 0.f;

    const float* kbase = &g_k[((size_t)(b * NKV + hk)) * SS * HD];
    const float* vbase = &g_v[((size_t)(b * NKV + hk)) * SS * HD];

    for (int k0 = 0; k0 < SS; k0 += 64) {
        // Load K (transposed) and V (row-major) tiles: 64 x 128 each
        {
            const float* ks = kbase + (size_t)k0 * HD;
            const float* vs = vbase + (size_t)k0 * HD;
            #pragma unroll
            for (int it = 0; it < 8; ++it) {
                int f4 = tid + it * 256;    // 0..2047 float4s (64 k x 32)
                int r  = f4 >> 5;           // k row 0..63
                int c4 = f4 & 31;           // d group
                float4 kv = *(const float4*)&ks[(size_t)r * HD + c4 * 4];
                Kt[(c4 * 4 + 0) * KTS + r] = kv.x;
                Kt[(c4 * 4 + 1) * KTS + r] = kv.y;
                Kt[(c4 * 4 + 2) * KTS + r] = kv.z;
                Kt[(c4 * 4 + 3) * KTS + r] = kv.w;
                float4 vv = *(const float4*)&vs[(size_t)r * HD + c4 * 4];
                *(float4*)&Vs[r * 128 + c4 * 4] = vv;
            }
        }
        __syncthreads();

        // Scores: 8x4 per thread
        float sc[8][4];
        #pragma unroll
        for (int i = 0; i < 8; ++i)
            #pragma unroll
            for (int j = 0; j < 4; ++j) sc[i][j] = 0.f;

        #pragma unroll 4
        for (int d = 0; d < 128; ++d) {
            float qa[8], kb[4];
            *(float4*)&qa[0] = *(const float4*)&Qt[d * QTS + ty * 8];
            *(float4*)&qa[4] = *(const float4*)&Qt[d * QTS + ty * 8 + 4];
            *(float4*)&kb[0] = *(const float4*)&Kt[d * KTS + tx * 4];
            #pragma unroll
            for (int i = 0; i < 8; ++i)
                #pragma unroll
                for (int j = 0; j < 4; ++j)
                    sc[i][j] = fmaf(qa[i], kb[j], sc[i][j]);
        }

        // Row maxes (per q row, across 16 tx groups)
        #pragma unroll
        for (int i = 0; i < 8; ++i) {
            float m = fmaxf(fmaxf(sc[i][0], sc[i][1]), fmaxf(sc[i][2], sc[i][3]));
            sRed[tx * SRS + ty * 8 + i] = m;
        }
        __syncthreads();

        if (tid < 128) {
            float m = sM[tid];
            float tm = -CUDART_INF_F;
            #pragma unroll
            for (int t = 0; t < 16; ++t) tm = fmaxf(tm, sRed[t * SRS + tid]);
            float mn = fmaxf(m, tm);
            sScale[tid] = __expf(m - mn);
            sMnew[tid]  = mn;
            sM[tid]     = mn;
        }
        __syncthreads();

        // Exp, write P, partial row sums, rescale O
        #pragma unroll
        for (int i = 0; i < 8; ++i) {
            float mn = sMnew[ty * 8 + i];
            float p0 = __expf(sc[i][0] - mn);
            float p1 = __expf(sc[i][1] - mn);
            float p2 = __expf(sc[i][2] - mn);
            float p3 = __expf(sc[i][3] - mn);
            *(float4*)&Ps[(ty * 8 + i) * PSS + tx * 4] = make_float4(p0, p1, p2, p3);
            sRed[tx * SRS + ty * 8 + i] = p0 + p1 + p2 + p3;
        }
        #pragma unroll
        for (int i = 0; i < 8; ++i) {
            float osc = sScale[ty * 8 + i];
            #pragma unroll
            for (int j = 0; j < 8; ++j) O[i][j] *= osc;
        }
        __syncthreads();

        if (tid < 128) {
            float s = 0.f;
            #pragma unroll
            for (int t = 0; t < 16; ++t) s += sRed[t * SRS + tid];
            sL[tid] = sL[tid] * sScale[tid] + s;
        }

        // PV: O[q][c] += sum_kk P[q][kk] * V[kk][c]
        #pragma unroll 4
        for (int kk = 0; kk < 64; ++kk) {
            float pv[8], vv[8];
            #pragma unroll
            for (int i = 0; i < 8; ++i) pv[i] = Ps[(ty * 8 + i) * PSS + kk];
            *(float4*)&vv[0] = *(const float4*)&Vs[kk * 128 + tx * 8];
            *(float4*)&vv[4] = *(const float4*)&Vs[kk * 128 + tx * 8 + 4];
            #pragma unroll
            for (int i = 0; i < 8; ++i)
                #pragma unroll
                for (int j = 0; j < 8; ++j)
                    O[i][j] = fmaf(pv[i], vv[j], O[i][j]);
        }
        __syncthreads();
    }

    // Normalize and write out: g_attn[b, s, h*128 + c]
    #pragma unroll
    for (int i = 0; i < 8; ++i) {
        int s = q0 + ty * 8 + i;
        float inv = 1.f / sL[ty * 8 + i];
        size_t off = (((size_t)b * SS + s) * NH + h) * HD + tx * 8;
        float4 v0 = make_float4(O[i][0] * inv, O[i][1] * inv, O[i][2] * inv, O[i][3] * inv);
        float4 v1 = make_float4(O[i][4] * inv, O[i][5] * inv, O[i][6] * inv, O[i][7] * inv);
        *(float4*)&g_attn[off] = v0;
        *(float4*)&g_attn[off + 4] = v1;
    }
}

// ---------------------------------------------------------------------------
extern "C" void kernel_launch(void* const* d_in, const int* in_sizes, int n_in,
                              void* d_out, int out_size)
{
    const float* hidden  = (const float*)d_in[0];
    const float* cos_t   = (const float*)d_in[1];
    const float* sin_t   = (const float*)d_in[2];
    const float* w_qkv   = (const float*)d_in[3];
    const float* q_ln    = (const float*)d_in[4];
    const float* k_ln    = (const float*)d_in[5];
    const float* w_dense = (const float*)d_in[6];
    float* out = (float*)d_out;

    void *p_qkv = nullptr, *p_attn = nullptr;
    cudaGetSymbolAddress(&p_qkv, g_qkv);
    cudaGetSymbolAddress(&p_attn, g_attn);
    float* qkv  = (float*)p_qkv;
    float* attn = (float*)p_attn;

    cudaFuncSetAttribute(attn_kernel, cudaFuncAttributeMaxDynamicSharedMemorySize,
                         ATTN_SMEM_BYTES);

    // 1) QKV projection: [4096,3072] = hidden[4096,2048] * w_qkv[3072,2048]^T
    gemm_tn_kernel<<<dim3(QKVO / 128, NTOK / 128), 256>>>(
        hidden, w_qkv, qkv, NTOK, QKVO, HID);

    // 2) RMSNorm + RoPE + split
    prep_kernel<<<dim3(NH + 2 * NKV, SS, BB), 128>>>(cos_t, sin_t, q_ln, k_ln);

    // 3) Flash attention (Q-tile 128)
    attn_kernel<<<dim3(SS / 128, BB * NH), 256, ATTN_SMEM_BYTES>>>();

    // 4) Output projection: [4096,2048] = attn[4096,2048] * w_dense[2048,2048]^T
    gemm_tn_kernel<<<dim3(HID / 128, NTOK / 128), 256>>>(
        attn, w_dense, out, NTOK, HID, HID);
}

// round 4
// speedup vs baseline: 1.6170x; 1.3923x over previous
#include <cuda_runtime.h>
#include <cuda_bf16.h>
#include <math_constants.h>
#include <cstdint>

// Problem dims
#define BB   2
#define SS   2048
#define HID  2048
#define NH   16
#define NKV  4
#define HD   128
#define RR   64
#define NTOK (BB*SS)          // 4096
#define QKVO ((NH+2*NKV)*HD)  // 3072

// Scratch (device globals; no allocation allowed)
__device__ float g_qkv[(size_t)NTOK * QKVO];
__device__ float g_q[(size_t)BB * NH  * SS * HD];
__device__ float g_k[(size_t)BB * NKV * SS * HD];
__device__ float g_v[(size_t)BB * NKV * SS * HD];
__device__ float g_attn[(size_t)NTOK * (NH*HD)];

// ---------------------------------------------------------------------------
// mma.sync m16n8k16 bf16 (base PTX, works on compute_103)
// ---------------------------------------------------------------------------
__device__ __forceinline__ void mma_bf16(float* c, const uint32_t* a, const uint32_t* b) {
    asm volatile(
        "mma.sync.aligned.m16n8k16.row.col.f32.bf16.bf16.f32 "
        "{%0,%1,%2,%3}, {%4,%5,%6,%7}, {%8,%9}, {%0,%1,%2,%3};"
        : "+f"(c[0]), "+f"(c[1]), "+f"(c[2]), "+f"(c[3])
        : "r"(a[0]), "r"(a[1]), "r"(a[2]), "r"(a[3]), "r"(b[0]), "r"(b[1]));
}

__device__ __forceinline__ uint32_t bf16hi2(float x, float y) {
    __nv_bfloat162 h = __floats2bfloat162_rn(x, y);
    return *(uint32_t*)&h;
}

// ---------------------------------------------------------------------------
// Tensor GEMM: C[M,N] = A[M,K] * B[N,K]^T, fp32 in/out, bf16 3-term split.
// 128x128 tile, BK=32, 256 threads (warps 2x4, warp tile 64x32).
// ---------------------------------------------------------------------------
#define TBK 32
#define ASTR 40                       // bf16 units per smem row (pad 32->40)
#define ARR (128 * ASTR)              // bf16 per array
#define STAGE_BF16 (4 * ARR)          // Ahi, Alo, Bhi, Blo
#define GEMM_SMEM (2 * STAGE_BF16 * 2)  // bytes (2 stages)

__global__ __launch_bounds__(256, 1) void gemm_mma_kernel(
    const float* __restrict__ A, const float* __restrict__ Bm,
    float* __restrict__ C, int N, int K)
{
    extern __shared__ __nv_bfloat16 smb[];
    const int tid  = threadIdx.x;
    const int wid  = tid >> 5;
    const int lane = tid & 31;
    const int wm   = wid >> 2;        // 0..1 -> m offset wm*64
    const int wn   = wid & 3;         // 0..3 -> n offset wn*32
    const int row0 = blockIdx.y * 128;
    const int col0 = blockIdx.x * 128;

    const int lr = lane >> 2;         // 0..7
    const int lc = (lane & 3) * 2;    // 0,2,4,6

    // loader indexing: each thread does 4 float4 per 128x32 tile
    const int ldr  = tid >> 3;        // row 0..31 (x4 iters -> 128)
    const int ldc4 = (tid & 7) * 4;   // col 0,4,...,28

    float acc[4][4][4];
    #pragma unroll
    for (int mt = 0; mt < 4; ++mt)
        #pragma unroll
        for (int nt = 0; nt < 4; ++nt)
            #pragma unroll
            for (int q = 0; q < 4; ++q) acc[mt][nt][q] = 0.f;

    const int nchunk = K / TBK;

    // convert+store one float4 into hi/lo arrays at row r, col c (bf16 units)
    auto put = [&](__nv_bfloat16* hi, __nv_bfloat16* lo, int r, int c, float4 v) {
        uint32_t h0 = bf16hi2(v.x, v.y);
        uint32_t h1 = bf16hi2(v.z, v.w);
        __nv_bfloat162 hh0 = *(__nv_bfloat162*)&h0;
        __nv_bfloat162 hh1 = *(__nv_bfloat162*)&h1;
        uint32_t l0 = bf16hi2(v.x - __bfloat162float(hh0.x), v.y - __bfloat162float(hh0.y));
        uint32_t l1 = bf16hi2(v.z - __bfloat162float(hh1.x), v.w - __bfloat162float(hh1.y));
        *(uint2*)&hi[r * ASTR + c] = make_uint2(h0, h1);
        *(uint2*)&lo[r * ASTR + c] = make_uint2(l0, l1);
    };

    // prefetch registers
    float4 pa[4], pb[4];

    // initial chunk load
    {
        const float* Ab = A + (size_t)row0 * K;
        const float* Bb = Bm + (size_t)col0 * K;
        __nv_bfloat16* s = smb;           // stage 0
        #pragma unroll
        for (int it = 0; it < 4; ++it) {
            int r = ldr + it * 32;
            float4 va = *(const float4*)&Ab[(size_t)r * K + ldc4];
            put(s, s + ARR, r, ldc4, va);
            float4 vb = *(const float4*)&Bb[(size_t)r * K + ldc4];
            put(s + 2 * ARR, s + 3 * ARR, r, ldc4, vb);
        }
    }
    __syncthreads();

    for (int ic = 0; ic < nchunk; ++ic) {
        const int cur = ic & 1;
        __nv_bfloat16* s = smb + cur * STAGE_BF16;
        __nv_bfloat16* Ahi = s;
        __nv_bfloat16* Alo = s + ARR;
        __nv_bfloat16* Bhi = s + 2 * ARR;
        __nv_bfloat16* Blo = s + 3 * ARR;

        // prefetch next chunk from gmem (overlaps with MMA below)
        if (ic + 1 < nchunk) {
            const float* Ab = A + (size_t)row0 * K + (ic + 1) * TBK;
            const float* Bb = Bm + (size_t)col0 * K + (ic + 1) * TBK;
            #pragma unroll
            for (int it = 0; it < 4; ++it) {
                int r = ldr + it * 32;
                pa[it] = *(const float4*)&Ab[(size_t)r * K + ldc4];
                pb[it] = *(const float4*)&Bb[(size_t)r * K + ldc4];
            }
        }

        // MMA over 2 k-steps of 16
        #pragma unroll
        for (int ks = 0; ks < 2; ++ks) {
            const int kk = ks * 16;
            uint32_t ah[4][4], al[4][4], bh[4][2], bl[4][2];
            #pragma unroll
            for (int mt = 0; mt < 4; ++mt) {
                int m0 = wm * 64 + mt * 16;
                const __nv_bfloat16* p0 = &Ahi[(m0 + lr) * ASTR + kk + lc];
                const __nv_bfloat16* p1 = &Alo[(m0 + lr) * ASTR + kk + lc];
                ah[mt][0] = *(const uint32_t*)p0;
                ah[mt][1] = *(const uint32_t*)(p0 + 8 * ASTR);
                ah[mt][2] = *(const uint32_t*)(p0 + 8);
                ah[mt][3] = *(const uint32_t*)(p0 + 8 * ASTR + 8);
                al[mt][0] = *(const uint32_t*)p1;
                al[mt][1] = *(const uint32_t*)(p1 + 8 * ASTR);
                al[mt][2] = *(const uint32_t*)(p1 + 8);
                al[mt][3] = *(const uint32_t*)(p1 + 8 * ASTR + 8);
            }
            #pragma unroll
            for (int nt = 0; nt < 4; ++nt) {
                int n0 = wn * 32 + nt * 8;
                const __nv_bfloat16* p0 = &Bhi[(n0 + lr) * ASTR + kk + lc];
                const __nv_bfloat16* p1 = &Blo[(n0 + lr) * ASTR + kk + lc];
                bh[nt][0] = *(const uint32_t*)p0;
                bh[nt][1] = *(const uint32_t*)(p0 + 8);
                bl[nt][0] = *(const uint32_t*)p1;
                bl[nt][1] = *(const uint32_t*)(p1 + 8);
            }
            #pragma unroll
            for (int mt = 0; mt < 4; ++mt)
                #pragma unroll
                for (int nt = 0; nt < 4; ++nt) {
                    mma_bf16(acc[mt][nt], ah[mt], bh[nt]);
                    mma_bf16(acc[mt][nt], ah[mt], bl[nt]);
                    mma_bf16(acc[mt][nt], al[mt], bh[nt]);
                }
        }

        // store prefetched chunk into other stage
        if (ic + 1 < nchunk) {
            __nv_bfloat16* d = smb + (1 - cur) * STAGE_BF16;
            #pragma unroll
            for (int it = 0; it < 4; ++it) {
                int r = ldr + it * 32;
                put(d, d + ARR, r, ldc4, pa[it]);
                put(d + 2 * ARR, d + 3 * ARR, r, ldc4, pb[it]);
            }
        }
        __syncthreads();
    }

    // epilogue
    #pragma unroll
    for (int mt = 0; mt < 4; ++mt) {
        int row = row0 + wm * 64 + mt * 16 + lr;
        #pragma unroll
        for (int nt = 0; nt < 4; ++nt) {
            int col = col0 + wn * 32 + nt * 8 + lc;
            *(float2*)&C[(size_t)row * N + col] =
                make_float2(acc[mt][nt][0], acc[mt][nt][1]);
            *(float2*)&C[(size_t)(row + 8) * N + col] =
                make_float2(acc[mt][nt][2], acc[mt][nt][3]);
        }
    }
}

// ---------------------------------------------------------------------------
// Per-head RMSNorm + RoPE + split into Q/K/V tensors.
// ---------------------------------------------------------------------------
__global__ __launch_bounds__(128) void prep_kernel(
    const float* __restrict__ cos_t, const float* __restrict__ sin_t,
    const float* __restrict__ q_ln, const float* __restrict__ k_ln)
{
    const int hh = blockIdx.x;
    const int s  = blockIdx.y;
    const int b  = blockIdx.z;
    const int d  = threadIdx.x;

    const size_t t = (size_t)b * SS + s;
    float x = g_qkv[t * QKVO + hh * HD + d];

    __shared__ float sy[HD];
    __shared__ float red[4];

    if (hh < NH + NKV) {
        float sq = x * x;
        #pragma unroll
        for (int o = 16; o; o >>= 1) sq += __shfl_xor_sync(0xFFFFFFFFu, sq, o);
        if ((d & 31) == 0) red[d >> 5] = sq;
        __syncthreads();
        float var = (red[0] + red[1] + red[2] + red[3]) * (1.f / HD);
        const float* w = (hh < NH) ? q_ln : k_ln;
        float y = x * rsqrtf(var + 1e-6f) * w[d];
        sy[d] = y;
        __syncthreads();

        float out = y;
        if (d < RR) {
            float c  = cos_t[t * RR + d];
            float sn = sin_t[t * RR + d];
            float rot = (d < RR / 2) ? -sy[d + RR / 2] : sy[d - RR / 2];
            out = fmaf(y, c, rot * sn);
        }
        if (hh < NH)
            g_q[(((size_t)(b * NH + hh)) * SS + s) * HD + d] = out;
        else
            g_k[(((size_t)(b * NKV + (hh - NH))) * SS + s) * HD + d] = out;
    } else {
        g_v[(((size_t)(b * NKV + (hh - NH - NKV))) * SS + s) * HD + d] = x;
    }
}

// ---------------------------------------------------------------------------
// Flash attention (round-3 version, FFMA, Q-tile 128)
// ---------------------------------------------------------------------------
#define QTS 136
#define KTS 72
#define PSS 72
#define SRS 129

#define ATTN_SMEM_FLOATS (128*QTS + 128*KTS + 64*128 + 128*PSS + 16*SRS + 4*128)
#define ATTN_SMEM_BYTES  (ATTN_SMEM_FLOATS * 4)

__global__ __launch_bounds__(256, 1) void attn_kernel()
{
    extern __shared__ float smf[];
    float* Qt    = smf;
    float* Kt    = Qt + 128 * QTS;
    float* Vs    = Kt + 128 * KTS;
    float* Ps    = Vs + 64 * 128;
    float* sRed  = Ps + 128 * PSS;
    float* sM    = sRed + 16 * SRS;
    float* sL    = sM + 128;
    float* sScale= sL + 128;
    float* sMnew = sScale + 128;

    const int tid = threadIdx.x;
    const int ty = tid >> 4;
    const int tx = tid & 15;
    const int q0 = blockIdx.x * 128;
    const int bh = blockIdx.y;
    const int b = bh >> 4;
    const int h = bh & 15;
    const int hk = h / (NH / NKV);

    const float qscale = 0.08838834764831845f;

    {
        const float* qsrc = &g_q[(((size_t)(b * NH + h)) * SS + q0) * HD];
        #pragma unroll
        for (int it = 0; it < 16; ++it) {
            int f4 = tid + it * 256;
            int r  = f4 >> 5;
            int c4 = f4 & 31;
            float4 v = *(const float4*)&qsrc[(size_t)r * HD + c4 * 4];
            Qt[(c4 * 4 + 0) * QTS + r] = v.x * qscale;
            Qt[(c4 * 4 + 1) * QTS + r] = v.y * qscale;
            Qt[(c4 * 4 + 2) * QTS + r] = v.z * qscale;
            Qt[(c4 * 4 + 3) * QTS + r] = v.w * qscale;
        }
        if (tid < 128) { sM[tid] = -CUDART_INF_F; sL[tid] = 0.f; }
    }
    __syncthreads();

    float O[8][8];
    #pragma unroll
    for (int i = 0; i < 8; ++i)
        #pragma unroll
        for (int j = 0; j < 8; ++j) O[i][j] = 0.f;

    const float* kbase = &g_k[((size_t)(b * NKV + hk)) * SS * HD];
    const float* vbase = &g_v[((size_t)(b * NKV + hk)) * SS * HD];

    for (int k0 = 0; k0 < SS; k0 += 64) {
        {
            const float* ks = kbase + (size_t)k0 * HD;
            const float* vs = vbase + (size_t)k0 * HD;
            #pragma unroll
            for (int it = 0; it < 8; ++it) {
                int f4 = tid + it * 256;
                int r  = f4 >> 5;
                int c4 = f4 & 31;
                float4 kv = *(const float4*)&ks[(size_t)r * HD + c4 * 4];
                Kt[(c4 * 4 + 0) * KTS + r] = kv.x;
                Kt[(c4 * 4 + 1) * KTS + r] = kv.y;
                Kt[(c4 * 4 + 2) * KTS + r] = kv.z;
                Kt[(c4 * 4 + 3) * KTS + r] = kv.w;
                float4 vv = *(const float4*)&vs[(size_t)r * HD + c4 * 4];
                *(float4*)&Vs[r * 128 + c4 * 4] = vv;
            }
        }
        __syncthreads();

        float sc[8][4];
        #pragma unroll
        for (int i = 0; i < 8; ++i)
            #pragma unroll
            for (int j = 0; j < 4; ++j) sc[i][j] = 0.f;

        #pragma unroll 4
        for (int d = 0; d < 128; ++d) {
            float qa[8], kb[4];
            *(float4*)&qa[0] = *(const float4*)&Qt[d * QTS + ty * 8];
            *(float4*)&qa[4] = *(const float4*)&Qt[d * QTS + ty * 8 + 4];
            *(float4*)&kb[0] = *(const float4*)&Kt[d * KTS + tx * 4];
            #pragma unroll
            for (int i = 0; i < 8; ++i)
                #pragma unroll
                for (int j = 0; j < 4; ++j)
                    sc[i][j] = fmaf(qa[i], kb[j], sc[i][j]);
        }

        #pragma unroll
        for (int i = 0; i < 8; ++i) {
            float m = fmaxf(fmaxf(sc[i][0], sc[i][1]), fmaxf(sc[i][2], sc[i][3]));
            sRed[tx * SRS + ty * 8 + i] = m;
        }
        __syncthreads();

        if (tid < 128) {
            float m = sM[tid];
            float tm = -CUDART_INF_F;
            #pragma unroll
            for (int t = 0; t < 16; ++t) tm = fmaxf(tm, sRed[t * SRS + tid]);
            float mn = fmaxf(m, tm);
            sScale[tid] = __expf(m - mn);
            sMnew[tid]  = mn;
            sM[tid]     = mn;
        }
        __syncthreads();

        #pragma unroll
        for (int i = 0; i < 8; ++i) {
            float mn = sMnew[ty * 8 + i];
            float p0 = __expf(sc[i][0] - mn);
            float p1 = __expf(sc[i][1] - mn);
            float p2 = __expf(sc[i][2] - mn);
            float p3 = __expf(sc[i][3] - mn);
            *(float4*)&Ps[(ty * 8 + i) * PSS + tx * 4] = make_float4(p0, p1, p2, p3);
            sRed[tx * SRS + ty * 8 + i] = p0 + p1 + p2 + p3;
        }
        #pragma unroll
        for (int i = 0; i < 8; ++i) {
            float osc = sScale[ty * 8 + i];
            #pragma unroll
            for (int j = 0; j < 8; ++j) O[i][j] *= osc;
        }
        __syncthreads();

        if (tid < 128) {
            float s = 0.f;
            #pragma unroll
            for (int t = 0; t < 16; ++t) s += sRed[t * SRS + tid];
            sL[tid] = sL[tid] * sScale[tid] + s;
        }

        #pragma unroll 4
        for (int kk = 0; kk < 64; ++kk) {
            float pv[8], vv[8];
            #pragma unroll
            for (int i = 0; i < 8; ++i) pv[i] = Ps[(ty * 8 + i) * PSS + kk];
            *(float4*)&vv[0] = *(const float4*)&Vs[kk * 128 + tx * 8];
            *(float4*)&vv[4] = *(const float4*)&Vs[kk * 128 + tx * 8 + 4];
            #pragma unroll
            for (int i = 0; i < 8; ++i)
                #pragma unroll
                for (int j = 0; j < 8; ++j)
                    O[i][j] = fmaf(pv[i], vv[j], O[i][j]);
        }
        __syncthreads();
    }

    #pragma unroll
    for (int i = 0; i < 8; ++i) {
        int s = q0 + ty * 8 + i;
        float inv = 1.f / sL[ty * 8 + i];
        size_t off = (((size_t)b * SS + s) * NH + h) * HD + tx * 8;
        float4 v0 = make_float4(O[i][0] * inv, O[i][1] * inv, O[i][2] * inv, O[i][3] * inv);
        float4 v1 = make_float4(O[i][4] * inv, O[i][5] * inv, O[i][6] * inv, O[i][7] * inv);
        *(float4*)&g_attn[off] = v0;
        *(float4*)&g_attn[off + 4] = v1;
    }
}

// ---------------------------------------------------------------------------
extern "C" void kernel_launch(void* const* d_in, const int* in_sizes, int n_in,
                              void* d_out, int out_size)
{
    const float* hidden  = (const float*)d_in[0];
    const float* cos_t   = (const float*)d_in[1];
    const float* sin_t   = (const float*)d_in[2];
    const float* w_qkv   = (const float*)d_in[3];
    const float* q_ln    = (const float*)d_in[4];
    const float* k_ln    = (const float*)d_in[5];
    const float* w_dense = (const float*)d_in[6];
    float* out = (float*)d_out;

    void *p_qkv = nullptr, *p_attn = nullptr;
    cudaGetSymbolAddress(&p_qkv, g_qkv);
    cudaGetSymbolAddress(&p_attn, g_attn);
    float* qkv  = (float*)p_qkv;
    float* attn = (float*)p_attn;

    cudaFuncSetAttribute(gemm_mma_kernel,
                         cudaFuncAttributeMaxDynamicSharedMemorySize, GEMM_SMEM);
    cudaFuncSetAttribute(attn_kernel,
                         cudaFuncAttributeMaxDynamicSharedMemorySize, ATTN_SMEM_BYTES);

    // 1) QKV projection
    gemm_mma_kernel<<<dim3(QKVO / 128, NTOK / 128), 256, GEMM_SMEM>>>(
        hidden, w_qkv, qkv, QKVO, HID);

    // 2) RMSNorm + RoPE + split
    prep_kernel<<<dim3(NH + 2 * NKV, SS, BB), 128>>>(cos_t, sin_t, q_ln, k_ln);

    // 3) Flash attention
    attn_kernel<<<dim3(SS / 128, BB * NH), 256, ATTN_SMEM_BYTES>>>();

    // 4) Output projection
    gemm_mma_kernel<<<dim3(HID / 128, NTOK / 128), 256, GEMM_SMEM>>>(
        attn, w_dense, out, HID, HID);
}

// round 5
// speedup vs baseline: 3.3407x; 2.0660x over previous
#include <cuda_runtime.h>
#include <cuda_bf16.h>
#include <math_constants.h>
#include <cstdint>

// Problem dims
#define BB   2
#define SS   2048
#define HID  2048
#define NH   16
#define NKV  4
#define HD   128
#define RR   64
#define NTOK (BB*SS)          // 4096
#define QKVO ((NH+2*NKV)*HD)  // 3072

// Scratch (device globals; no allocation allowed)
__device__ float g_qkv[(size_t)NTOK * QKVO];
__device__ float g_q[(size_t)BB * NH  * SS * HD];
__device__ float g_k[(size_t)BB * NKV * SS * HD];
__device__ float g_v[(size_t)BB * NKV * SS * HD];
__device__ float g_attn[(size_t)NTOK * (NH*HD)];

// ---------------------------------------------------------------------------
// mma.sync m16n8k16 bf16 (base PTX, works on compute_103)
// ---------------------------------------------------------------------------
__device__ __forceinline__ void mma_bf16(float* c, const uint32_t* a, const uint32_t* b) {
    asm volatile(
        "mma.sync.aligned.m16n8k16.row.col.f32.bf16.bf16.f32 "
        "{%0,%1,%2,%3}, {%4,%5,%6,%7}, {%8,%9}, {%0,%1,%2,%3};"
        : "+f"(c[0]), "+f"(c[1]), "+f"(c[2]), "+f"(c[3])
        : "r"(a[0]), "r"(a[1]), "r"(a[2]), "r"(a[3]), "r"(b[0]), "r"(b[1]));
}

__device__ __forceinline__ uint32_t bf16hi2(float x, float y) {
    __nv_bfloat162 h = __floats2bfloat162_rn(x, y);
    return *(uint32_t*)&h;
}

// split float4 into bf16 hi pair-words and lo pair-words
__device__ __forceinline__ void split4(float4 v, uint2& hi, uint2& lo) {
    uint32_t h0 = bf16hi2(v.x, v.y);
    uint32_t h1 = bf16hi2(v.z, v.w);
    __nv_bfloat162 hh0 = *(__nv_bfloat162*)&h0;
    __nv_bfloat162 hh1 = *(__nv_bfloat162*)&h1;
    uint32_t l0 = bf16hi2(v.x - __bfloat162float(hh0.x), v.y - __bfloat162float(hh0.y));
    uint32_t l1 = bf16hi2(v.z - __bfloat162float(hh1.x), v.w - __bfloat162float(hh1.y));
    hi = make_uint2(h0, h1);
    lo = make_uint2(l0, l1);
}

// ---------------------------------------------------------------------------
// Tensor GEMM: C[M,N] = A[M,K] * B[N,K]^T, fp32 in/out, bf16 3-term split.
// (proven round 4: 475 TF/s effective)
// ---------------------------------------------------------------------------
#define TBK 32
#define ASTR 40
#define ARR (128 * ASTR)
#define STAGE_BF16 (4 * ARR)
#define GEMM_SMEM (2 * STAGE_BF16 * 2)

__global__ __launch_bounds__(256, 1) void gemm_mma_kernel(
    const float* __restrict__ A, const float* __restrict__ Bm,
    float* __restrict__ C, int N, int K)
{
    extern __shared__ __nv_bfloat16 smb[];
    const int tid  = threadIdx.x;
    const int wid  = tid >> 5;
    const int lane = tid & 31;
    const int wm   = wid >> 2;
    const int wn   = wid & 3;
    const int row0 = blockIdx.y * 128;
    const int col0 = blockIdx.x * 128;

    const int lr = lane >> 2;
    const int lc = (lane & 3) * 2;

    const int ldr  = tid >> 3;
    const int ldc4 = (tid & 7) * 4;

    float acc[4][4][4];
    #pragma unroll
    for (int mt = 0; mt < 4; ++mt)
        #pragma unroll
        for (int nt = 0; nt < 4; ++nt)
            #pragma unroll
            for (int q = 0; q < 4; ++q) acc[mt][nt][q] = 0.f;

    const int nchunk = K / TBK;

    auto put = [&](__nv_bfloat16* hi, __nv_bfloat16* lo, int r, int c, float4 v) {
        uint2 h, l;
        split4(v, h, l);
        *(uint2*)&hi[r * ASTR + c] = h;
        *(uint2*)&lo[r * ASTR + c] = l;
    };

    float4 pa[4], pb[4];

    {
        const float* Ab = A + (size_t)row0 * K;
        const float* Bb = Bm + (size_t)col0 * K;
        __nv_bfloat16* s = smb;
        #pragma unroll
        for (int it = 0; it < 4; ++it) {
            int r = ldr + it * 32;
            float4 va = *(const float4*)&Ab[(size_t)r * K + ldc4];
            put(s, s + ARR, r, ldc4, va);
            float4 vb = *(const float4*)&Bb[(size_t)r * K + ldc4];
            put(s + 2 * ARR, s + 3 * ARR, r, ldc4, vb);
        }
    }
    __syncthreads();

    for (int ic = 0; ic < nchunk; ++ic) {
        const int cur = ic & 1;
        __nv_bfloat16* s = smb + cur * STAGE_BF16;
        __nv_bfloat16* Ahi = s;
        __nv_bfloat16* Alo = s + ARR;
        __nv_bfloat16* Bhi = s + 2 * ARR;
        __nv_bfloat16* Blo = s + 3 * ARR;

        if (ic + 1 < nchunk) {
            const float* Ab = A + (size_t)row0 * K + (ic + 1) * TBK;
            const float* Bb = Bm + (size_t)col0 * K + (ic + 1) * TBK;
            #pragma unroll
            for (int it = 0; it < 4; ++it) {
                int r = ldr + it * 32;
                pa[it] = *(const float4*)&Ab[(size_t)r * K + ldc4];
                pb[it] = *(const float4*)&Bb[(size_t)r * K + ldc4];
            }
        }

        #pragma unroll
        for (int ks = 0; ks < 2; ++ks) {
            const int kk = ks * 16;
            uint32_t ah[4][4], al[4][4], bh[4][2], bl[4][2];
            #pragma unroll
            for (int mt = 0; mt < 4; ++mt) {
                int m0 = wm * 64 + mt * 16;
                const __nv_bfloat16* p0 = &Ahi[(m0 + lr) * ASTR + kk + lc];
                const __nv_bfloat16* p1 = &Alo[(m0 + lr) * ASTR + kk + lc];
                ah[mt][0] = *(const uint32_t*)p0;
                ah[mt][1] = *(const uint32_t*)(p0 + 8 * ASTR);
                ah[mt][2] = *(const uint32_t*)(p0 + 8);
                ah[mt][3] = *(const uint32_t*)(p0 + 8 * ASTR + 8);
                al[mt][0] = *(const uint32_t*)p1;
                al[mt][1] = *(const uint32_t*)(p1 + 8 * ASTR);
                al[mt][2] = *(const uint32_t*)(p1 + 8);
                al[mt][3] = *(const uint32_t*)(p1 + 8 * ASTR + 8);
            }
            #pragma unroll
            for (int nt = 0; nt < 4; ++nt) {
                int n0 = wn * 32 + nt * 8;
                const __nv_bfloat16* p0 = &Bhi[(n0 + lr) * ASTR + kk + lc];
                const __nv_bfloat16* p1 = &Blo[(n0 + lr) * ASTR + kk + lc];
                bh[nt][0] = *(const uint32_t*)p0;
                bh[nt][1] = *(const uint32_t*)(p0 + 8);
                bl[nt][0] = *(const uint32_t*)p1;
                bl[nt][1] = *(const uint32_t*)(p1 + 8);
            }
            #pragma unroll
            for (int mt = 0; mt < 4; ++mt)
                #pragma unroll
                for (int nt = 0; nt < 4; ++nt) {
                    mma_bf16(acc[mt][nt], ah[mt], bh[nt]);
                    mma_bf16(acc[mt][nt], ah[mt], bl[nt]);
                    mma_bf16(acc[mt][nt], al[mt], bh[nt]);
                }
        }

        if (ic + 1 < nchunk) {
            __nv_bfloat16* d = smb + (1 - cur) * STAGE_BF16;
            #pragma unroll
            for (int it = 0; it < 4; ++it) {
                int r = ldr + it * 32;
                put(d, d + ARR, r, ldc4, pa[it]);
                put(d + 2 * ARR, d + 3 * ARR, r, ldc4, pb[it]);
            }
        }
        __syncthreads();
    }

    #pragma unroll
    for (int mt = 0; mt < 4; ++mt) {
        int row = row0 + wm * 64 + mt * 16 + lr;
        #pragma unroll
        for (int nt = 0; nt < 4; ++nt) {
            int col = col0 + wn * 32 + nt * 8 + lc;
            *(float2*)&C[(size_t)row * N + col] =
                make_float2(acc[mt][nt][0], acc[mt][nt][1]);
            *(float2*)&C[(size_t)(row + 8) * N + col] =
                make_float2(acc[mt][nt][2], acc[mt][nt][3]);
        }
    }
}

// ---------------------------------------------------------------------------
// Per-head RMSNorm + RoPE + split into Q/K/V tensors.
// ---------------------------------------------------------------------------
__global__ __launch_bounds__(128) void prep_kernel(
    const float* __restrict__ cos_t, const float* __restrict__ sin_t,
    const float* __restrict__ q_ln, const float* __restrict__ k_ln)
{
    const int hh = blockIdx.x;
    const int s  = blockIdx.y;
    const int b  = blockIdx.z;
    const int d  = threadIdx.x;

    const size_t t = (size_t)b * SS + s;
    float x = g_qkv[t * QKVO + hh * HD + d];

    __shared__ float sy[HD];
    __shared__ float red[4];

    if (hh < NH + NKV) {
        float sq = x * x;
        #pragma unroll
        for (int o = 16; o; o >>= 1) sq += __shfl_xor_sync(0xFFFFFFFFu, sq, o);
        if ((d & 31) == 0) red[d >> 5] = sq;
        __syncthreads();
        float var = (red[0] + red[1] + red[2] + red[3]) * (1.f / HD);
        const float* w = (hh < NH) ? q_ln : k_ln;
        float y = x * rsqrtf(var + 1e-6f) * w[d];
        sy[d] = y;
        __syncthreads();

        float out = y;
        if (d < RR) {
            float c  = cos_t[t * RR + d];
            float sn = sin_t[t * RR + d];
            float rot = (d < RR / 2) ? -sy[d + RR / 2] : sy[d - RR / 2];
            out = fmaf(y, c, rot * sn);
        }
        if (hh < NH)
            g_q[(((size_t)(b * NH + hh)) * SS + s) * HD + d] = out;
        else
            g_k[(((size_t)(b * NKV + (hh - NH))) * SS + s) * HD + d] = out;
    } else {
        g_v[(((size_t)(b * NKV + (hh - NH - NKV))) * SS + s) * HD + d] = x;
    }
}

// ---------------------------------------------------------------------------
// Flash attention on mma.sync (bf16 3-term split for S and PV).
// CTA: 128 q x (b,h). 8 warps; warp owns 16 q-rows x full 64-k tile.
// K smem: row-major [k][d]; V smem: transposed [c][k]. Online softmax in regs.
// ---------------------------------------------------------------------------
#define DSTR 136   // bf16 stride for Q/K rows (d=128 + pad 8) -> 4 words mod 32
#define VSTR 72    // bf16 stride for Vt rows (k=64 + pad 8)   -> 4 words mod 32

#define AQ_OFF  0                         // Qhi[128*DSTR], Qlo
#define AK_OFF  (2 * 128 * DSTR)          // Khi[64*DSTR],  Klo
#define AV_OFF  (AK_OFF + 2 * 64 * DSTR)  // Vhi[128*VSTR], Vlo
#define ATTN2_BF16 (AV_OFF + 2 * 128 * VSTR)
#define ATTN2_SMEM (ATTN2_BF16 * 2)       // bytes (~141 KB)

__global__ __launch_bounds__(256, 1) void attn_mma_kernel()
{
    extern __shared__ __nv_bfloat16 smb[];
    __nv_bfloat16* Qhi = smb + AQ_OFF;
    __nv_bfloat16* Qlo = Qhi + 128 * DSTR;
    __nv_bfloat16* Khi = smb + AK_OFF;
    __nv_bfloat16* Klo = Khi + 64 * DSTR;
    __nv_bfloat16* Vhi = smb + AV_OFF;
    __nv_bfloat16* Vlo = Vhi + 128 * VSTR;

    const int tid  = threadIdx.x;
    const int wid  = tid >> 5;
    const int lane = tid & 31;
    const int gr   = lane >> 2;        // 0..7
    const int gc   = (lane & 3) * 2;   // 0,2,4,6
    const int q0 = blockIdx.x * 128;
    const int bh = blockIdx.y;
    const int b = bh >> 4;
    const int h = bh & 15;
    const int hk = h / (NH / NKV);

    const float qscale = 0.08838834764831845f;  // 1/sqrt(128)

    // ---- load Q tile 128x128, pre-scaled, split hi/lo ----
    {
        const float* qsrc = &g_q[(((size_t)(b * NH + h)) * SS + q0) * HD];
        #pragma unroll
        for (int it = 0; it < 16; ++it) {
            int f4 = tid + it * 256;       // 128 rows x 32 float4
            int r  = f4 >> 5;
            int c4 = f4 & 31;
            float4 v = *(const float4*)&qsrc[(size_t)r * HD + c4 * 4];
            v.x *= qscale; v.y *= qscale; v.z *= qscale; v.w *= qscale;
            uint2 hi, lo;
            split4(v, hi, lo);
            *(uint2*)&Qhi[r * DSTR + c4 * 4] = hi;
            *(uint2*)&Qlo[r * DSTR + c4 * 4] = lo;
        }
    }

    float m_[2] = {-CUDART_INF_F, -CUDART_INF_F};
    float l_[2] = {0.f, 0.f};
    float O[16][4];
    #pragma unroll
    for (int nt = 0; nt < 16; ++nt)
        #pragma unroll
        for (int q = 0; q < 4; ++q) O[nt][q] = 0.f;

    const float* kbase = &g_k[((size_t)(b * NKV + hk)) * SS * HD];
    const float* vbase = &g_v[((size_t)(b * NKV + hk)) * SS * HD];
    const int m0 = wid * 16;

    __syncthreads();

    for (int kt = 0; kt < SS / 64; ++kt) {
        // ---- load K tile 64x128 (row-major) ----
        {
            const float* ks = kbase + (size_t)kt * 64 * HD;
            #pragma unroll
            for (int it = 0; it < 8; ++it) {
                int f4 = tid + it * 256;   // 64 rows x 32 float4
                int r  = f4 >> 5;
                int c4 = f4 & 31;
                float4 v = *(const float4*)&ks[(size_t)r * HD + c4 * 4];
                uint2 hi, lo;
                split4(v, hi, lo);
                *(uint2*)&Khi[r * DSTR + c4 * 4] = hi;
                *(uint2*)&Klo[r * DSTR + c4 * 4] = lo;
            }
        }
        // ---- load V tile 64x128, store transposed Vt[c][k] ----
        {
            const float* vs = vbase + (size_t)kt * 64 * HD;
            #pragma unroll
            for (int it = 0; it < 8; ++it) {
                int id = tid + it * 256;   // 16 kgroups x 128 c
                int kg = id >> 7;          // 0..15 (4 k each)
                int c  = id & 127;
                float4 v = make_float4(vs[(size_t)(kg * 4 + 0) * HD + c],
                                       vs[(size_t)(kg * 4 + 1) * HD + c],
                                       vs[(size_t)(kg * 4 + 2) * HD + c],
                                       vs[(size_t)(kg * 4 + 3) * HD + c]);
                uint2 hi, lo;
                split4(v, hi, lo);
                *(uint2*)&Vhi[c * VSTR + kg * 4] = hi;
                *(uint2*)&Vlo[c * VSTR + kg * 4] = lo;
            }
        }
        __syncthreads();

        // ---- S = Q K^T: warp rows [m0, m0+16), cols 0..63 (8 n-tiles) ----
        float sc[8][4];
        #pragma unroll
        for (int nt = 0; nt < 8; ++nt)
            #pragma unroll
            for (int q = 0; q < 4; ++q) sc[nt][q] = 0.f;

        #pragma unroll
        for (int ks = 0; ks < 8; ++ks) {
            const int kk = ks * 16;
            uint32_t qh[4], ql[4];
            {
                const __nv_bfloat16* p0 = &Qhi[(m0 + gr) * DSTR + kk + gc];
                const __nv_bfloat16* p1 = &Qlo[(m0 + gr) * DSTR + kk + gc];
                qh[0] = *(const uint32_t*)p0;
                qh[1] = *(const uint32_t*)(p0 + 8 * DSTR);
                qh[2] = *(const uint32_t*)(p0 + 8);
                qh[3] = *(const uint32_t*)(p0 + 8 * DSTR + 8);
                ql[0] = *(const uint32_t*)p1;
                ql[1] = *(const uint32_t*)(p1 + 8 * DSTR);
                ql[2] = *(const uint32_t*)(p1 + 8);
                ql[3] = *(const uint32_t*)(p1 + 8 * DSTR + 8);
            }
            #pragma unroll
            for (int nt = 0; nt < 8; ++nt) {
                uint32_t kb[2], klb[2];
                const __nv_bfloat16* p0 = &Khi[(nt * 8 + gr) * DSTR + kk + gc];
                const __nv_bfloat16* p1 = &Klo[(nt * 8 + gr) * DSTR + kk + gc];
                kb[0]  = *(const uint32_t*)p0;
                kb[1]  = *(const uint32_t*)(p0 + 8);
                klb[0] = *(const uint32_t*)p1;
                klb[1] = *(const uint32_t*)(p1 + 8);
                mma_bf16(sc[nt], qh, kb);
                mma_bf16(sc[nt], qh, klb);
                mma_bf16(sc[nt], ql, kb);
            }
        }

        // ---- online softmax (warp-local; rows gr and gr+8) ----
        float mx0 = -CUDART_INF_F, mx1 = -CUDART_INF_F;
        #pragma unroll
        for (int nt = 0; nt < 8; ++nt) {
            mx0 = fmaxf(mx0, fmaxf(sc[nt][0], sc[nt][1]));
            mx1 = fmaxf(mx1, fmaxf(sc[nt][2], sc[nt][3]));
        }
        mx0 = fmaxf(mx0, __shfl_xor_sync(0xFFFFFFFFu, mx0, 1));
        mx0 = fmaxf(mx0, __shfl_xor_sync(0xFFFFFFFFu, mx0, 2));
        mx1 = fmaxf(mx1, __shfl_xor_sync(0xFFFFFFFFu, mx1, 1));
        mx1 = fmaxf(mx1, __shfl_xor_sync(0xFFFFFFFFu, mx1, 2));

        float mn0 = fmaxf(m_[0], mx0);
        float mn1 = fmaxf(m_[1], mx1);
        float scl0 = __expf(m_[0] - mn0);
        float scl1 = __expf(m_[1] - mn1);
        m_[0] = mn0; m_[1] = mn1;

        // exp, pack P hi/lo A-fragments, row sums
        uint32_t pah[4][4], pal[4][4];
        float rs0 = 0.f, rs1 = 0.f;
        #pragma unroll
        for (int k2 = 0; k2 < 4; ++k2) {
            float p00 = __expf(sc[2*k2][0] - mn0);
            float p01 = __expf(sc[2*k2][1] - mn0);
            float p02 = __expf(sc[2*k2][2] - mn1);
            float p03 = __expf(sc[2*k2][3] - mn1);
            float p10 = __expf(sc[2*k2+1][0] - mn0);
            float p11 = __expf(sc[2*k2+1][1] - mn0);
            float p12 = __expf(sc[2*k2+1][2] - mn1);
            float p13 = __expf(sc[2*k2+1][3] - mn1);
            rs0 += p00 + p01 + p10 + p11;
            rs1 += p02 + p03 + p12 + p13;
            uint32_t h;
            h = bf16hi2(p00, p01); pah[k2][0] = h;
            {   __nv_bfloat162 hh = *(__nv_bfloat162*)&h;
                pal[k2][0] = bf16hi2(p00 - __bfloat162float(hh.x), p01 - __bfloat162float(hh.y)); }
            h = bf16hi2(p02, p03); pah[k2][1] = h;
            {   __nv_bfloat162 hh = *(__nv_bfloat162*)&h;
                pal[k2][1] = bf16hi2(p02 - __bfloat162float(hh.x), p03 - __bfloat162float(hh.y)); }
            h = bf16hi2(p10, p11); pah[k2][2] = h;
            {   __nv_bfloat162 hh = *(__nv_bfloat162*)&h;
                pal[k2][2] = bf16hi2(p10 - __bfloat162float(hh.x), p11 - __bfloat162float(hh.y)); }
            h = bf16hi2(p12, p13); pah[k2][3] = h;
            {   __nv_bfloat162 hh = *(__nv_bfloat162*)&h;
                pal[k2][3] = bf16hi2(p12 - __bfloat162float(hh.x), p13 - __bfloat162float(hh.y)); }
        }
        rs0 += __shfl_xor_sync(0xFFFFFFFFu, rs0, 1);
        rs0 += __shfl_xor_sync(0xFFFFFFFFu, rs0, 2);
        rs1 += __shfl_xor_sync(0xFFFFFFFFu, rs1, 1);
        rs1 += __shfl_xor_sync(0xFFFFFFFFu, rs1, 2);
        l_[0] = l_[0] * scl0 + rs0;
        l_[1] = l_[1] * scl1 + rs1;

        // rescale O
        #pragma unroll
        for (int nt = 0; nt < 16; ++nt) {
            O[nt][0] *= scl0; O[nt][1] *= scl0;
            O[nt][2] *= scl1; O[nt][3] *= scl1;
        }

        // ---- PV: O[16 rows][128 cols] += P[16x64] * V[64x128] ----
        #pragma unroll
        for (int k2 = 0; k2 < 4; ++k2) {
            const int kk = k2 * 16;
            #pragma unroll
            for (int nt = 0; nt < 16; ++nt) {
                uint32_t vb[2], vlb[2];
                const __nv_bfloat16* p0 = &Vhi[(nt * 8 + gr) * VSTR + kk + gc];
                const __nv_bfloat16* p1 = &Vlo[(nt * 8 + gr) * VSTR + kk + gc];
                vb[0]  = *(const uint32_t*)p0;
                vb[1]  = *(const uint32_t*)(p0 + 8);
                vlb[0] = *(const uint32_t*)p1;
                vlb[1] = *(const uint32_t*)(p1 + 8);
                mma_bf16(O[nt], pah[k2], vb);
                mma_bf16(O[nt], pah[k2], vlb);
                mma_bf16(O[nt], pal[k2], vb);
            }
        }
        __syncthreads();
    }

    // ---- epilogue: normalize, write g_attn[b, s, h*128 + c] ----
    const float inv0 = 1.f / l_[0];
    const float inv1 = 1.f / l_[1];
    const int s0 = q0 + m0 + gr;
    #pragma unroll
    for (int nt = 0; nt < 16; ++nt) {
        int col = nt * 8 + gc;
        size_t off0 = (((size_t)b * SS + s0) * NH + h) * HD + col;
        size_t off1 = (((size_t)b * SS + s0 + 8) * NH + h) * HD + col;
        *(float2*)&g_attn[off0] = make_float2(O[nt][0] * inv0, O[nt][1] * inv0);
        *(float2*)&g_attn[off1] = make_float2(O[nt][2] * inv1, O[nt][3] * inv1);
    }
}

// ---------------------------------------------------------------------------
extern "C" void kernel_launch(void* const* d_in, const int* in_sizes, int n_in,
                              void* d_out, int out_size)
{
    const float* hidden  = (const float*)d_in[0];
    const float* cos_t   = (const float*)d_in[1];
    const float* sin_t   = (const float*)d_in[2];
    const float* w_qkv   = (const float*)d_in[3];
    const float* q_ln    = (const float*)d_in[4];
    const float* k_ln    = (const float*)d_in[5];
    const float* w_dense = (const float*)d_in[6];
    float* out = (float*)d_out;

    void *p_qkv = nullptr, *p_attn = nullptr;
    cudaGetSymbolAddress(&p_qkv, g_qkv);
    cudaGetSymbolAddress(&p_attn, g_attn);
    float* qkv  = (float*)p_qkv;
    float* attn = (float*)p_attn;

    cudaFuncSetAttribute(gemm_mma_kernel,
                         cudaFuncAttributeMaxDynamicSharedMemorySize, GEMM_SMEM);
    cudaFuncSetAttribute(attn_mma_kernel,
                         cudaFuncAttributeMaxDynamicSharedMemorySize, ATTN2_SMEM);

    // 1) QKV projection
    gemm_mma_kernel<<<dim3(QKVO / 128, NTOK / 128), 256, GEMM_SMEM>>>(
        hidden, w_qkv, qkv, QKVO, HID);

    // 2) RMSNorm + RoPE + split
    prep_kernel<<<dim3(NH + 2 * NKV, SS, BB), 128>>>(cos_t, sin_t, q_ln, k_ln);

    // 3) Flash attention (tensor cores)
    attn_mma_kernel<<<dim3(SS / 128, BB * NH), 256, ATTN2_SMEM>>>();

    // 4) Output projection
    gemm_mma_kernel<<<dim3(HID / 128, NTOK / 128), 256, GEMM_SMEM>>>(
        attn, w_dense, out, HID, HID);
}

// round 6
// speedup vs baseline: 3.5575x; 1.0649x over previous
#include <cuda_runtime.h>
#include <cuda_bf16.h>
#include <math_constants.h>
#include <cstdint>

// Problem dims
#define BB   2
#define SS   2048
#define HID  2048
#define NH   16
#define NKV  4
#define HD   128
#define RR   64
#define NTOK (BB*SS)          // 4096
#define QKVO ((NH+2*NKV)*HD)  // 3072

// Scratch (device globals; no allocation allowed)
__device__ float g_qkv[(size_t)NTOK * QKVO];
__device__ float g_q[(size_t)BB * NH  * SS * HD];
__device__ float g_k[(size_t)BB * NKV * SS * HD];
__device__ float g_v[(size_t)BB * NKV * SS * HD];
__device__ float g_attn[(size_t)NTOK * (NH*HD)];

// ---------------------------------------------------------------------------
// PTX helpers (base PTX only — compute_103-safe)
// ---------------------------------------------------------------------------
__device__ __forceinline__ void mma_bf16(float* c, const uint32_t* a, const uint32_t* b) {
    asm volatile(
        "mma.sync.aligned.m16n8k16.row.col.f32.bf16.bf16.f32 "
        "{%0,%1,%2,%3}, {%4,%5,%6,%7}, {%8,%9}, {%0,%1,%2,%3};"
        : "+f"(c[0]), "+f"(c[1]), "+f"(c[2]), "+f"(c[3])
        : "r"(a[0]), "r"(a[1]), "r"(a[2]), "r"(a[3]), "r"(b[0]), "r"(b[1]));
}

__device__ __forceinline__ void ldsm_x4(uint32_t* r, uint32_t addr) {
    asm volatile("ldmatrix.sync.aligned.m8n8.x4.shared.b16 {%0,%1,%2,%3}, [%4];"
        : "=r"(r[0]), "=r"(r[1]), "=r"(r[2]), "=r"(r[3]) : "r"(addr));
}

__device__ __forceinline__ void ldsm_x4_t(uint32_t* r, uint32_t addr) {
    asm volatile("ldmatrix.sync.aligned.m8n8.x4.trans.shared.b16 {%0,%1,%2,%3}, [%4];"
        : "=r"(r[0]), "=r"(r[1]), "=r"(r[2]), "=r"(r[3]) : "r"(addr));
}

__device__ __forceinline__ uint32_t smem_u32(const void* p) {
    uint32_t a;
    asm("{ .reg .u64 t; cvta.to.shared.u64 t, %1; cvt.u32.u64 %0, t; }"
        : "=r"(a) : "l"(p));
    return a;
}

__device__ __forceinline__ uint32_t bf16hi2(float x, float y) {
    __nv_bfloat162 h = __floats2bfloat162_rn(x, y);
    return *(uint32_t*)&h;
}

// split float4 into bf16 hi pair-words and lo pair-words
__device__ __forceinline__ void split4(float4 v, uint2& hi, uint2& lo) {
    uint32_t h0 = bf16hi2(v.x, v.y);
    uint32_t h1 = bf16hi2(v.z, v.w);
    __nv_bfloat162 hh0 = *(__nv_bfloat162*)&h0;
    __nv_bfloat162 hh1 = *(__nv_bfloat162*)&h1;
    uint32_t l0 = bf16hi2(v.x - __bfloat162float(hh0.x), v.y - __bfloat162float(hh0.y));
    uint32_t l1 = bf16hi2(v.z - __bfloat162float(hh1.x), v.w - __bfloat162float(hh1.y));
    hi = make_uint2(h0, h1);
    lo = make_uint2(l0, l1);
}

// ---------------------------------------------------------------------------
// Tensor GEMM: C[M,N] = A[M,K] * B[N,K]^T, fp32 in/out, bf16 3-term split.
// 128x128 tile, BK=32, 256 threads (warps 2x4, warp tile 64x32). ldmatrix loads.
// ---------------------------------------------------------------------------
#define TBK 32
#define ASTR 40
#define ARR (128 * ASTR)
#define STAGE_BF16 (4 * ARR)
#define GEMM_SMEM (2 * STAGE_BF16 * 2)

__global__ __launch_bounds__(256, 1) void gemm_mma_kernel(
    const float* __restrict__ A, const float* __restrict__ Bm,
    float* __restrict__ C, int N, int K)
{
    extern __shared__ __nv_bfloat16 smb[];
    const int tid  = threadIdx.x;
    const int wid  = tid >> 5;
    const int lane = tid & 31;
    const int wm   = wid >> 2;
    const int wn   = wid & 3;
    const int row0 = blockIdx.y * 128;
    const int col0 = blockIdx.x * 128;

    const int lr = lane >> 2;
    const int lc = (lane & 3) * 2;

    const int ldr  = tid >> 3;
    const int ldc4 = (tid & 7) * 4;

    const uint32_t sb = smem_u32(smb);
    // ldmatrix lane offsets (bytes)
    const uint32_t laneA = ((lane & 15) * ASTR + (lane >> 4) * 8) * 2;
    const uint32_t laneB = (((lane >> 4) * 8 + (lane & 7)) * ASTR + ((lane >> 3) & 1) * 8) * 2;

    float acc[4][4][4];
    #pragma unroll
    for (int mt = 0; mt < 4; ++mt)
        #pragma unroll
        for (int nt = 0; nt < 4; ++nt)
            #pragma unroll
            for (int q = 0; q < 4; ++q) acc[mt][nt][q] = 0.f;

    const int nchunk = K / TBK;

    auto put = [&](__nv_bfloat16* hi, __nv_bfloat16* lo, int r, int c, float4 v) {
        uint2 h, l;
        split4(v, h, l);
        *(uint2*)&hi[r * ASTR + c] = h;
        *(uint2*)&lo[r * ASTR + c] = l;
    };

    float4 pa[4], pb[4];

    {
        const float* Ab = A + (size_t)row0 * K;
        const float* Bb = Bm + (size_t)col0 * K;
        __nv_bfloat16* s = smb;
        #pragma unroll
        for (int it = 0; it < 4; ++it) {
            int r = ldr + it * 32;
            float4 va = *(const float4*)&Ab[(size_t)r * K + ldc4];
            put(s, s + ARR, r, ldc4, va);
            float4 vb = *(const float4*)&Bb[(size_t)r * K + ldc4];
            put(s + 2 * ARR, s + 3 * ARR, r, ldc4, vb);
        }
    }
    __syncthreads();

    for (int ic = 0; ic < nchunk; ++ic) {
        const int cur = ic & 1;
        const uint32_t stOff = (uint32_t)cur * (STAGE_BF16 * 2);
        const uint32_t aBase = sb + stOff + (uint32_t)(wm * 64) * (ASTR * 2) + laneA;
        const uint32_t bBase = sb + stOff + (uint32_t)(2 * ARR) * 2
                             + (uint32_t)(wn * 32) * (ASTR * 2) + laneB;

        if (ic + 1 < nchunk) {
            const float* Ab = A + (size_t)row0 * K + (ic + 1) * TBK;
            const float* Bb = Bm + (size_t)col0 * K + (ic + 1) * TBK;
            #pragma unroll
            for (int it = 0; it < 4; ++it) {
                int r = ldr + it * 32;
                pa[it] = *(const float4*)&Ab[(size_t)r * K + ldc4];
                pb[it] = *(const float4*)&Bb[(size_t)r * K + ldc4];
            }
        }

        #pragma unroll
        for (int ks = 0; ks < 2; ++ks) {
            const uint32_t kkB = ks * 32;   // 16 bf16 = 32 bytes
            uint32_t ah[4][4], al[4][4], bh[2][4], bl[2][4];
            #pragma unroll
            for (int mt = 0; mt < 4; ++mt) {
                ldsm_x4(ah[mt], aBase + (uint32_t)mt * (16 * ASTR * 2) + kkB);
                ldsm_x4(al[mt], aBase + (uint32_t)(ARR * 2) + (uint32_t)mt * (16 * ASTR * 2) + kkB);
            }
            #pragma unroll
            for (int np = 0; np < 2; ++np) {
                ldsm_x4(bh[np], bBase + (uint32_t)np * (16 * ASTR * 2) + kkB);
                ldsm_x4(bl[np], bBase + (uint32_t)(ARR * 2) + (uint32_t)np * (16 * ASTR * 2) + kkB);
            }
            #pragma unroll
            for (int mt = 0; mt < 4; ++mt)
                #pragma unroll
                for (int nt = 0; nt < 4; ++nt) {
                    const uint32_t* pbh = &bh[nt >> 1][(nt & 1) * 2];
                    const uint32_t* pbl = &bl[nt >> 1][(nt & 1) * 2];
                    mma_bf16(acc[mt][nt], ah[mt], pbh);
                    mma_bf16(acc[mt][nt], ah[mt], pbl);
                    mma_bf16(acc[mt][nt], al[mt], pbh);
                }
        }

        if (ic + 1 < nchunk) {
            __nv_bfloat16* d = smb + (1 - cur) * STAGE_BF16;
            #pragma unroll
            for (int it = 0; it < 4; ++it) {
                int r = ldr + it * 32;
                put(d, d + ARR, r, ldc4, pa[it]);
                put(d + 2 * ARR, d + 3 * ARR, r, ldc4, pb[it]);
            }
        }
        __syncthreads();
    }

    #pragma unroll
    for (int mt = 0; mt < 4; ++mt) {
        int row = row0 + wm * 64 + mt * 16 + lr;
        #pragma unroll
        for (int nt = 0; nt < 4; ++nt) {
            int col = col0 + wn * 32 + nt * 8 + lc;
            *(float2*)&C[(size_t)row * N + col] =
                make_float2(acc[mt][nt][0], acc[mt][nt][1]);
            *(float2*)&C[(size_t)(row + 8) * N + col] =
                make_float2(acc[mt][nt][2], acc[mt][nt][3]);
        }
    }
}

// ---------------------------------------------------------------------------
// Per-head RMSNorm + RoPE + split into Q/K/V tensors.
// ---------------------------------------------------------------------------
__global__ __launch_bounds__(128) void prep_kernel(
    const float* __restrict__ cos_t, const float* __restrict__ sin_t,
    const float* __restrict__ q_ln, const float* __restrict__ k_ln)
{
    const int hh = blockIdx.x;
    const int s  = blockIdx.y;
    const int b  = blockIdx.z;
    const int d  = threadIdx.x;

    const size_t t = (size_t)b * SS + s;
    float x = g_qkv[t * QKVO + hh * HD + d];

    __shared__ float sy[HD];
    __shared__ float red[4];

    if (hh < NH + NKV) {
        float sq = x * x;
        #pragma unroll
        for (int o = 16; o; o >>= 1) sq += __shfl_xor_sync(0xFFFFFFFFu, sq, o);
        if ((d & 31) == 0) red[d >> 5] = sq;
        __syncthreads();
        float var = (red[0] + red[1] + red[2] + red[3]) * (1.f / HD);
        const float* w = (hh < NH) ? q_ln : k_ln;
        float y = x * rsqrtf(var + 1e-6f) * w[d];
        sy[d] = y;
        __syncthreads();

        float out = y;
        if (d < RR) {
            float c  = cos_t[t * RR + d];
            float sn = sin_t[t * RR + d];
            float rot = (d < RR / 2) ? -sy[d + RR / 2] : sy[d - RR / 2];
            out = fmaf(y, c, rot * sn);
        }
        if (hh < NH)
            g_q[(((size_t)(b * NH + hh)) * SS + s) * HD + d] = out;
        else
            g_k[(((size_t)(b * NKV + (hh - NH))) * SS + s) * HD + d] = out;
    } else {
        g_v[(((size_t)(b * NKV + (hh - NH - NKV))) * SS + s) * HD + d] = x;
    }
}

// ---------------------------------------------------------------------------
// Flash attention on mma.sync (bf16 3-term split for S and PV), ldmatrix loads.
// CTA: 128 q x (b,h). 8 warps; warp owns 16 q-rows x full 64-k tile.
// Q,K,V smem all row-major [row][d or k], V B-fragments via ldmatrix.trans.
// ---------------------------------------------------------------------------
#define DSTR 136   // bf16 stride (d=128 + pad 8); 272B rows, LDSM conflict-free

#define AQ_OFF  0                         // Qhi[128*DSTR], Qlo
#define AK_OFF  (2 * 128 * DSTR)          // Khi[64*DSTR],  Klo
#define AV_OFF  (AK_OFF + 2 * 64 * DSTR)  // Vhi[64*DSTR],  Vlo
#define ATTN2_BF16 (AV_OFF + 2 * 64 * DSTR)
#define ATTN2_SMEM (ATTN2_BF16 * 2)       // ~136 KB

__global__ __launch_bounds__(256, 1) void attn_mma_kernel()
{
    extern __shared__ __nv_bfloat16 smb[];
    __nv_bfloat16* Qhi = smb + AQ_OFF;
    __nv_bfloat16* Qlo = Qhi + 128 * DSTR;
    __nv_bfloat16* Khi = smb + AK_OFF;
    __nv_bfloat16* Klo = Khi + 64 * DSTR;
    __nv_bfloat16* Vhi = smb + AV_OFF;
    __nv_bfloat16* Vlo = Vhi + 64 * DSTR;

    const int tid  = threadIdx.x;
    const int wid  = tid >> 5;
    const int lane = tid & 31;
    const int gr   = lane >> 2;
    const int gc   = (lane & 3) * 2;
    const int q0 = blockIdx.x * 128;
    const int bh = blockIdx.y;
    const int b = bh >> 4;
    const int h = bh & 15;
    const int hk = h / (NH / NKV);
    const int m0 = wid * 16;

    const float qscale = 0.08838834764831845f;  // 1/sqrt(128)

    const uint32_t sb = smem_u32(smb);
    // ldmatrix lane offsets (bytes)
    const uint32_t laneA = ((lane & 15) * DSTR + (lane >> 4) * 8) * 2;      // A-frag (row,k)
    const uint32_t laneB = (((lane >> 4) * 8 + (lane & 7)) * DSTR + ((lane >> 3) & 1) * 8) * 2;
    const uint32_t laneV = ((lane & 15) * DSTR + (lane >> 4) * 8) * 2;      // trans: (k,d)

    const uint32_t qBaseHi = sb + (uint32_t)(m0 * DSTR) * 2 + laneA;
    const uint32_t qBaseLo = qBaseHi + (uint32_t)(128 * DSTR) * 2;
    const uint32_t kBaseHi = sb + (uint32_t)AK_OFF * 2 + laneB;
    const uint32_t kBaseLo = kBaseHi + (uint32_t)(64 * DSTR) * 2;
    const uint32_t vBaseHi = sb + (uint32_t)AV_OFF * 2 + laneV;
    const uint32_t vBaseLo = vBaseHi + (uint32_t)(64 * DSTR) * 2;

    // ---- load Q tile 128x128, pre-scaled, split hi/lo ----
    {
        const float* qsrc = &g_q[(((size_t)(b * NH + h)) * SS + q0) * HD];
        #pragma unroll
        for (int it = 0; it < 16; ++it) {
            int f4 = tid + it * 256;
            int r  = f4 >> 5;
            int c4 = f4 & 31;
            float4 v = *(const float4*)&qsrc[(size_t)r * HD + c4 * 4];
            v.x *= qscale; v.y *= qscale; v.z *= qscale; v.w *= qscale;
            uint2 hi, lo;
            split4(v, hi, lo);
            *(uint2*)&Qhi[r * DSTR + c4 * 4] = hi;
            *(uint2*)&Qlo[r * DSTR + c4 * 4] = lo;
        }
    }

    float m_[2] = {-CUDART_INF_F, -CUDART_INF_F};
    float l_[2] = {0.f, 0.f};
    float O[16][4];
    #pragma unroll
    for (int nt = 0; nt < 16; ++nt)
        #pragma unroll
        for (int q = 0; q < 4; ++q) O[nt][q] = 0.f;

    const float* kbase = &g_k[((size_t)(b * NKV + hk)) * SS * HD];
    const float* vbase = &g_v[((size_t)(b * NKV + hk)) * SS * HD];

    __syncthreads();

    for (int kt = 0; kt < SS / 64; ++kt) {
        // ---- load K and V tiles 64x128 (row-major), split hi/lo ----
        {
            const float* ks = kbase + (size_t)kt * 64 * HD;
            const float* vs = vbase + (size_t)kt * 64 * HD;
            #pragma unroll
            for (int it = 0; it < 8; ++it) {
                int f4 = tid + it * 256;
                int r  = f4 >> 5;
                int c4 = f4 & 31;
                float4 v = *(const float4*)&ks[(size_t)r * HD + c4 * 4];
                uint2 hi, lo;
                split4(v, hi, lo);
                *(uint2*)&Khi[r * DSTR + c4 * 4] = hi;
                *(uint2*)&Klo[r * DSTR + c4 * 4] = lo;
                float4 w = *(const float4*)&vs[(size_t)r * HD + c4 * 4];
                split4(w, hi, lo);
                *(uint2*)&Vhi[r * DSTR + c4 * 4] = hi;
                *(uint2*)&Vlo[r * DSTR + c4 * 4] = lo;
            }
        }
        __syncthreads();

        // ---- S = Q K^T: warp rows [m0, m0+16), cols 0..63 (8 n-tiles) ----
        float sc[8][4];
        #pragma unroll
        for (int nt = 0; nt < 8; ++nt)
            #pragma unroll
            for (int q = 0; q < 4; ++q) sc[nt][q] = 0.f;

        #pragma unroll
        for (int ks = 0; ks < 8; ++ks) {
            const uint32_t kkB = ks * 32;
            uint32_t qh[4], ql[4];
            ldsm_x4(qh, qBaseHi + kkB);
            ldsm_x4(ql, qBaseLo + kkB);
            #pragma unroll
            for (int np = 0; np < 4; ++np) {
                uint32_t kb4[4], kl4[4];
                ldsm_x4(kb4, kBaseHi + (uint32_t)np * (16 * DSTR * 2) + kkB);
                ldsm_x4(kl4, kBaseLo + (uint32_t)np * (16 * DSTR * 2) + kkB);
                mma_bf16(sc[2*np],   qh, &kb4[0]);
                mma_bf16(sc[2*np],   qh, &kl4[0]);
                mma_bf16(sc[2*np],   ql, &kb4[0]);
                mma_bf16(sc[2*np+1], qh, &kb4[2]);
                mma_bf16(sc[2*np+1], qh, &kl4[2]);
                mma_bf16(sc[2*np+1], ql, &kb4[2]);
            }
        }

        // ---- online softmax (warp-local; rows gr and gr+8) ----
        float mx0 = -CUDART_INF_F, mx1 = -CUDART_INF_F;
        #pragma unroll
        for (int nt = 0; nt < 8; ++nt) {
            mx0 = fmaxf(mx0, fmaxf(sc[nt][0], sc[nt][1]));
            mx1 = fmaxf(mx1, fmaxf(sc[nt][2], sc[nt][3]));
        }
        mx0 = fmaxf(mx0, __shfl_xor_sync(0xFFFFFFFFu, mx0, 1));
        mx0 = fmaxf(mx0, __shfl_xor_sync(0xFFFFFFFFu, mx0, 2));
        mx1 = fmaxf(mx1, __shfl_xor_sync(0xFFFFFFFFu, mx1, 1));
        mx1 = fmaxf(mx1, __shfl_xor_sync(0xFFFFFFFFu, mx1, 2));

        float mn0 = fmaxf(m_[0], mx0);
        float mn1 = fmaxf(m_[1], mx1);
        float scl0 = __expf(m_[0] - mn0);
        float scl1 = __expf(m_[1] - mn1);
        m_[0] = mn0; m_[1] = mn1;

        uint32_t pah[4][4], pal[4][4];
        float rs0 = 0.f, rs1 = 0.f;
        #pragma unroll
        for (int k2 = 0; k2 < 4; ++k2) {
            float p00 = __expf(sc[2*k2][0] - mn0);
            float p01 = __expf(sc[2*k2][1] - mn0);
            float p02 = __expf(sc[2*k2][2] - mn1);
            float p03 = __expf(sc[2*k2][3] - mn1);
            float p10 = __expf(sc[2*k2+1][0] - mn0);
            float p11 = __expf(sc[2*k2+1][1] - mn0);
            float p12 = __expf(sc[2*k2+1][2] - mn1);
            float p13 = __expf(sc[2*k2+1][3] - mn1);
            rs0 += p00 + p01 + p10 + p11;
            rs1 += p02 + p03 + p12 + p13;
            uint32_t hh;
            hh = bf16hi2(p00, p01); pah[k2][0] = hh;
            {   __nv_bfloat162 t = *(__nv_bfloat162*)&hh;
                pal[k2][0] = bf16hi2(p00 - __bfloat162float(t.x), p01 - __bfloat162float(t.y)); }
            hh = bf16hi2(p02, p03); pah[k2][1] = hh;
            {   __nv_bfloat162 t = *(__nv_bfloat162*)&hh;
                pal[k2][1] = bf16hi2(p02 - __bfloat162float(t.x), p03 - __bfloat162float(t.y)); }
            hh = bf16hi2(p10, p11); pah[k2][2] = hh;
            {   __nv_bfloat162 t = *(__nv_bfloat162*)&hh;
                pal[k2][2] = bf16hi2(p10 - __bfloat162float(t.x), p11 - __bfloat162float(t.y)); }
            hh = bf16hi2(p12, p13); pah[k2][3] = hh;
            {   __nv_bfloat162 t = *(__nv_bfloat162*)&hh;
                pal[k2][3] = bf16hi2(p12 - __bfloat162float(t.x), p13 - __bfloat162float(t.y)); }
        }
        rs0 += __shfl_xor_sync(0xFFFFFFFFu, rs0, 1);
        rs0 += __shfl_xor_sync(0xFFFFFFFFu, rs0, 2);
        rs1 += __shfl_xor_sync(0xFFFFFFFFu, rs1, 1);
        rs1 += __shfl_xor_sync(0xFFFFFFFFu, rs1, 2);
        l_[0] = l_[0] * scl0 + rs0;
        l_[1] = l_[1] * scl1 + rs1;

        #pragma unroll
        for (int nt = 0; nt < 16; ++nt) {
            O[nt][0] *= scl0; O[nt][1] *= scl0;
            O[nt][2] *= scl1; O[nt][3] *= scl1;
        }

        // ---- PV: O[16 rows][128 cols] += P[16x64] * V[64x128] (trans B frags) ----
        #pragma unroll
        for (int k2 = 0; k2 < 4; ++k2) {
            const uint32_t kOff = (uint32_t)k2 * (16 * DSTR * 2);
            #pragma unroll
            for (int np = 0; np < 8; ++np) {
                uint32_t vb4[4], vl4[4];
                ldsm_x4_t(vb4, vBaseHi + kOff + (uint32_t)np * 32);
                ldsm_x4_t(vl4, vBaseLo + kOff + (uint32_t)np * 32);
                mma_bf16(O[2*np],   pah[k2], &vb4[0]);
                mma_bf16(O[2*np],   pah[k2], &vl4[0]);
                mma_bf16(O[2*np],   pal[k2], &vb4[0]);
                mma_bf16(O[2*np+1], pah[k2], &vb4[2]);
                mma_bf16(O[2*np+1], pah[k2], &vl4[2]);
                mma_bf16(O[2*np+1], pal[k2], &vb4[2]);
            }
        }
        __syncthreads();
    }

    // ---- epilogue: normalize, write g_attn[b, s, h*128 + c] ----
    const float inv0 = 1.f / l_[0];
    const float inv1 = 1.f / l_[1];
    const int s0 = q0 + m0 + gr;
    #pragma unroll
    for (int nt = 0; nt < 16; ++nt) {
        int col = nt * 8 + gc;
        size_t off0 = (((size_t)b * SS + s0) * NH + h) * HD + col;
        size_t off1 = (((size_t)b * SS + s0 + 8) * NH + h) * HD + col;
        *(float2*)&g_attn[off0] = make_float2(O[nt][0] * inv0, O[nt][1] * inv0);
        *(float2*)&g_attn[off1] = make_float2(O[nt][2] * inv1, O[nt][3] * inv1);
    }
}

// ---------------------------------------------------------------------------
extern "C" void kernel_launch(void* const* d_in, const int* in_sizes, int n_in,
                              void* d_out, int out_size)
{
    const float* hidden  = (const float*)d_in[0];
    const float* cos_t   = (const float*)d_in[1];
    const float* sin_t   = (const float*)d_in[2];
    const float* w_qkv   = (const float*)d_in[3];
    const float* q_ln    = (const float*)d_in[4];
    const float* k_ln    = (const float*)d_in[5];
    const float* w_dense = (const float*)d_in[6];
    float* out = (float*)d_out;

    void *p_qkv = nullptr, *p_attn = nullptr;
    cudaGetSymbolAddress(&p_qkv, g_qkv);
    cudaGetSymbolAddress(&p_attn, g_attn);
    float* qkv  = (float*)p_qkv;
    float* attn = (float*)p_attn;

    cudaFuncSetAttribute(gemm_mma_kernel,
                         cudaFuncAttributeMaxDynamicSharedMemorySize, GEMM_SMEM);
    cudaFuncSetAttribute(attn_mma_kernel,
                         cudaFuncAttributeMaxDynamicSharedMemorySize, ATTN2_SMEM);

    // 1) QKV projection
    gemm_mma_kernel<<<dim3(QKVO / 128, NTOK / 128), 256, GEMM_SMEM>>>(
        hidden, w_qkv, qkv, QKVO, HID);

    // 2) RMSNorm + RoPE + split
    prep_kernel<<<dim3(NH + 2 * NKV, SS, BB), 128>>>(cos_t, sin_t, q_ln, k_ln);

    // 3) Flash attention (tensor cores + ldmatrix)
    attn_mma_kernel<<<dim3(SS / 128, BB * NH), 256, ATTN2_SMEM>>>();

    // 4) Output projection
    gemm_mma_kernel<<<dim3(HID / 128, NTOK / 128), 256, GEMM_SMEM>>>(
        attn, w_dense, out, HID, HID);
}